// round 14
// baseline (speedup 1.0000x reference)
#include <cuda_runtime.h>
#include <cuda_bf16.h>
#include <math.h>
#include <stdint.h>

#define BATCH 2
#define NHEAD 8
#define NLAYER 6
#define STOT 5440   // 4096+1024+256+64

// ---------------- scratch (static device globals; no runtime allocation) ----------------
__device__ float g_lat[BATCH * 256 * 4096];
__device__ float g_o[BATCH * 256 * 4096];
__device__ float g_col[BATCH * 2304 * 4096];
__device__ float g_ft[BATCH * 4096 * 256];
__device__ float g_wt[1310720];
__device__ float g_ms[BATCH * 256 * STOT];
__device__ float g_src[BATCH * STOT * 256];
__device__ float g_pos[STOT * 256];
__device__ float g_refpt[STOT * 2];
__device__ float g_q[BATCH * STOT * 256];
__device__ float g_val[BATCH * STOT * 256];
__device__ float g_off[BATCH * STOT * 256];
__device__ float g_aw[BATCH * STOT * 128];
__device__ float g_attn[BATCH * STOT * 256];
__device__ float g_tmp[BATCH * STOT * 256];
__device__ float g_ffn[BATCH * STOT * 2048];

// ---------------- helpers ----------------
__device__ __forceinline__ uint32_t smem_u32(const void* p) {
    uint32_t a;
    asm("{ .reg .u64 t; cvta.to.shared.u64 t, %1; cvt.u32.u64 %0, t; }" : "=r"(a) : "l"(p));
    return a;
}
__device__ __forceinline__ void ldm_x4(uint32_t& r0, uint32_t& r1, uint32_t& r2, uint32_t& r3,
                                       uint32_t addr) {
    asm volatile("ldmatrix.sync.aligned.m8n8.x4.shared.b16 {%0,%1,%2,%3}, [%4];"
                 : "=r"(r0), "=r"(r1), "=r"(r2), "=r"(r3) : "r"(addr));
}
__device__ __forceinline__ void mma_bf16(float* d, const uint32_t* a, const uint32_t* b) {
    asm volatile(
        "mma.sync.aligned.m16n8k16.row.col.f32.bf16.bf16.f32 "
        "{%0,%1,%2,%3}, {%4,%5,%6,%7}, {%8,%9}, {%0,%1,%2,%3};"
        : "+f"(d[0]), "+f"(d[1]), "+f"(d[2]), "+f"(d[3])
        : "r"(a[0]), "r"(a[1]), "r"(a[2]), "r"(a[3]), "r"(b[0]), "r"(b[1]));
}

// ============ HMMA bf16x3 GEMM (R7 core + occupancy-2 launch bound) ============
// C[M,N] = A[M,K] * B[N,K]^T (+bias)(+relu). A,B fp32 in GMEM, K-major rows.
// grid = (N/128, M/128, batch), 256 threads. K % 32 == 0.
#define PITCH 40   // bf16 elems per smem row (32 data + 8 pad -> 80B pitch, ldmatrix conflict-free)

__global__ __launch_bounds__(256, 2)
void gx(const float* __restrict__ A, const float* __restrict__ B, float* __restrict__ C,
        int K, int lda, int ldb, int ldc,
        long long sA, long long sB, long long sC,
        const float* __restrict__ bias, int bias_mode, int relu) {
    A += (long long)blockIdx.z * sA;
    B += (long long)blockIdx.z * sB;
    C += (long long)blockIdx.z * sC;

    __shared__ __align__(16) uint16_t AsH[128][PITCH];
    __shared__ __align__(16) uint16_t AsL[128][PITCH];
    __shared__ __align__(16) uint16_t BsH[128][PITCH];
    __shared__ __align__(16) uint16_t BsL[128][PITCH];

    int tid = threadIdx.x;
    int lane = tid & 31, w = tid >> 5;
    int row0 = blockIdx.y * 128, col0 = blockIdx.x * 128;

    // loader mapping: 8 lanes cover one row's 32 floats
    int lr = tid >> 3;          // 0..31
    int lk = (tid & 7) * 4;     // 0,4,...,28
    const float* Ap = A + (long long)(row0 + lr) * lda + lk;
    const float* Bp = B + (long long)(col0 + lr) * ldb + lk;

    // warp tile: 4 (M) x 2 (N) warps; warp = 32 (M) x 64 (N)
    int m0 = (w >> 1) * 32;
    int n0 = (w & 1) * 64;

    uint32_t ah_base = smem_u32(&AsH[0][0]);
    uint32_t al_base = smem_u32(&AsL[0][0]);
    uint32_t bh_base = smem_u32(&BsH[0][0]);
    uint32_t bl_base = smem_u32(&BsL[0][0]);

    // ldmatrix per-thread row/col offsets
    int lrow = ((lane >> 3) & 1) * 8 + (lane & 7);
    int lcol = ((lane >> 4) & 1) * 8;

    float acc[2][8][4];
#pragma unroll
    for (int i = 0; i < 2; i++)
#pragma unroll
        for (int j = 0; j < 8; j++)
#pragma unroll
            for (int q = 0; q < 4; q++) acc[i][j][q] = 0.f;

    int nst = K >> 5;
    float4 pa[4], pb[4];
#pragma unroll
    for (int i = 0; i < 4; i++) {
        pa[i] = *(const float4*)(Ap + (long long)i * 32 * lda);
        pb[i] = *(const float4*)(Bp + (long long)i * 32 * ldb);
    }

    for (int s = 0; s < nst; s++) {
        // ---- convert + split + store to smem ----
#pragma unroll
        for (int i = 0; i < 4; i++) {
            int r = lr + i * 32;
            float4 v = pa[i];
            __nv_bfloat162 h01 = __floats2bfloat162_rn(v.x, v.y);
            __nv_bfloat162 h23 = __floats2bfloat162_rn(v.z, v.w);
            __nv_bfloat162 l01 = __floats2bfloat162_rn(v.x - __bfloat162float(h01.x),
                                                       v.y - __bfloat162float(h01.y));
            __nv_bfloat162 l23 = __floats2bfloat162_rn(v.z - __bfloat162float(h23.x),
                                                       v.w - __bfloat162float(h23.y));
            *(uint32_t*)&AsH[r][lk] = *(uint32_t*)&h01;
            *(uint32_t*)&AsH[r][lk + 2] = *(uint32_t*)&h23;
            *(uint32_t*)&AsL[r][lk] = *(uint32_t*)&l01;
            *(uint32_t*)&AsL[r][lk + 2] = *(uint32_t*)&l23;

            v = pb[i];
            h01 = __floats2bfloat162_rn(v.x, v.y);
            h23 = __floats2bfloat162_rn(v.z, v.w);
            l01 = __floats2bfloat162_rn(v.x - __bfloat162float(h01.x),
                                        v.y - __bfloat162float(h01.y));
            l23 = __floats2bfloat162_rn(v.z - __bfloat162float(h23.x),
                                        v.w - __bfloat162float(h23.y));
            *(uint32_t*)&BsH[r][lk] = *(uint32_t*)&h01;
            *(uint32_t*)&BsH[r][lk + 2] = *(uint32_t*)&h23;
            *(uint32_t*)&BsL[r][lk] = *(uint32_t*)&l01;
            *(uint32_t*)&BsL[r][lk + 2] = *(uint32_t*)&l23;
        }
        __syncthreads();

        // prefetch next stage while computing this one
        if (s + 1 < nst) {
            int k0 = (s + 1) << 5;
#pragma unroll
            for (int i = 0; i < 4; i++) {
                pa[i] = *(const float4*)(Ap + (long long)i * 32 * lda + k0);
                pb[i] = *(const float4*)(Bp + (long long)i * 32 * ldb + k0);
            }
        }

        // ---- compute: 2 x k16 sub-steps ----
#pragma unroll
        for (int kk = 0; kk < 2; kk++) {
            int kc = kk * 16 + lcol;
            uint32_t aH[2][4], aL[2][4], bH[8][2], bL[8][2];
#pragma unroll
            for (int ma = 0; ma < 2; ma++) {
                uint32_t off = (uint32_t)((m0 + ma * 16 + lrow) * PITCH + kc) * 2;
                ldm_x4(aH[ma][0], aH[ma][1], aH[ma][2], aH[ma][3], ah_base + off);
                ldm_x4(aL[ma][0], aL[ma][1], aL[ma][2], aL[ma][3], al_base + off);
            }
#pragma unroll
            for (int ng = 0; ng < 4; ng++) {
                uint32_t off = (uint32_t)((n0 + ng * 16 + lrow) * PITCH + kc) * 2;
                uint32_t r0, r1, r2, r3;
                ldm_x4(r0, r1, r2, r3, bh_base + off);
                bH[ng * 2][0] = r0; bH[ng * 2][1] = r2;
                bH[ng * 2 + 1][0] = r1; bH[ng * 2 + 1][1] = r3;
                ldm_x4(r0, r1, r2, r3, bl_base + off);
                bL[ng * 2][0] = r0; bL[ng * 2][1] = r2;
                bL[ng * 2 + 1][0] = r1; bL[ng * 2 + 1][1] = r3;
            }
#pragma unroll
            for (int ma = 0; ma < 2; ma++)
#pragma unroll
                for (int na = 0; na < 8; na++) {
                    mma_bf16(acc[ma][na], aH[ma], bH[na]);
                    mma_bf16(acc[ma][na], aH[ma], bL[na]);
                    mma_bf16(acc[ma][na], aL[ma], bH[na]);
                }
        }
        __syncthreads();
    }

    // ---- epilogue ----
    int g = lane >> 2;
    int t2 = (lane & 3) * 2;
#pragma unroll
    for (int ma = 0; ma < 2; ma++) {
#pragma unroll
        for (int na = 0; na < 8; na++) {
            int mA = row0 + m0 + ma * 16 + g;
            int nA = col0 + n0 + na * 8 + t2;
            float b0 = 0.f, b1 = 0.f;
            if (bias_mode == 2) { b0 = bias[nA]; b1 = bias[nA + 1]; }
            float bmA = (bias_mode == 1) ? bias[mA] : 0.f;
            float bmB = (bias_mode == 1) ? bias[mA + 8] : 0.f;
            float2 o0, o1;
            o0.x = acc[ma][na][0] + bmA + b0;
            o0.y = acc[ma][na][1] + bmA + b1;
            o1.x = acc[ma][na][2] + bmB + b0;
            o1.y = acc[ma][na][3] + bmB + b1;
            if (relu) {
                o0.x = fmaxf(o0.x, 0.f); o0.y = fmaxf(o0.y, 0.f);
                o1.x = fmaxf(o1.x, 0.f); o1.y = fmaxf(o1.y, 0.f);
            }
            *(float2*)(C + (long long)mA * ldc + nA) = o0;
            *(float2*)(C + (long long)(mA + 8) * ldc + nA) = o1;
        }
    }
}

// ---------------- small fp32 GEMM (64x64x16), level 3 ----------------
__global__ void gemm64(const float* __restrict__ A, const float* __restrict__ B,
                       float* __restrict__ C,
                       int M, int N, int K, int lda, int ldb, int ldc,
                       long long sA, long long sB, long long sC,
                       const float* __restrict__ bias, int bias_mode, int relu) {
    A += (long long)blockIdx.z * sA;
    B += (long long)blockIdx.z * sB;
    C += (long long)blockIdx.z * sC;

    __shared__ float As[16][64];
    __shared__ float Bs[16][64];

    int tid = threadIdx.x;
    int tr = tid >> 4, tc = tid & 15;
    int row0 = blockIdx.y * 64, col0 = blockIdx.x * 64;

    int ar = tid >> 2;
    int ak = (tid & 3) * 4;
    int bk = tid >> 4;
    int bn = (tid & 15) * 4;

    float acc[4][4] = {};

    for (int k0 = 0; k0 < K; k0 += 16) {
        float4 a4 = *(const float4*)(A + (long long)(row0 + ar) * lda + k0 + ak);
        As[ak + 0][ar] = a4.x;
        As[ak + 1][ar] = a4.y;
        As[ak + 2][ar] = a4.z;
        As[ak + 3][ar] = a4.w;
        float4 b4 = *(const float4*)(B + (long long)(k0 + bk) * ldb + col0 + bn);
        *(float4*)&Bs[bk][bn] = b4;
        __syncthreads();

#pragma unroll
        for (int k = 0; k < 16; k++) {
            float4 av = *(const float4*)&As[k][tr * 4];
            float4 bv = *(const float4*)&Bs[k][tc * 4];
            float aa[4] = {av.x, av.y, av.z, av.w};
            float bb[4] = {bv.x, bv.y, bv.z, bv.w};
#pragma unroll
            for (int i = 0; i < 4; i++)
#pragma unroll
                for (int j = 0; j < 4; j++) acc[i][j] += aa[i] * bb[j];
        }
        __syncthreads();
    }

#pragma unroll
    for (int i = 0; i < 4; i++) {
        int m = row0 + tr * 4 + i;
        float bm = (bias_mode == 1) ? bias[m] : 0.f;
#pragma unroll
        for (int j = 0; j < 4; j++) {
            int n = col0 + tc * 4 + j;
            float v = acc[i][j] + bm + ((bias_mode == 2) ? bias[n] : 0.f);
            if (relu) v = fmaxf(v, 0.f);
            C[(long long)m * ldc + n] = v;
        }
    }
}

// ---------------- transposes ----------------
__global__ void transw_kernel(const float* __restrict__ in, float* __restrict__ out, int K, int N) {
    int idx = blockIdx.x * blockDim.x + threadIdx.x;
    if (idx >= K * N) return;
    int k = idx % K, n = idx / K;
    out[(long long)n * K + k] = in[(long long)k * N + n];
}

__global__ void trfeat_kernel(const float* __restrict__ in, float* __restrict__ out, int C, int HW) {
    int idx = blockIdx.x * blockDim.x + threadIdx.x;
    int total = BATCH * C * HW;
    if (idx >= total) return;
    int c = idx % C;
    int p = (idx / C) % HW;
    int b = idx / (C * HW);
    out[idx] = in[((long long)b * C + c) * HW + p];
}

// ---------------- GroupNorm ----------------
__global__ void gn_kernel(const float* __restrict__ in, float* __restrict__ out,
                          const float* __restrict__ sc, const float* __restrict__ bi,
                          int HW, int relu) {
    int b = blockIdx.y, g = blockIdx.x;
    long long base = ((long long)b * 256 + g * 8) * HW;
    int n = 8 * HW;
    float s = 0.f, s2 = 0.f;
    for (int i = threadIdx.x; i < n; i += blockDim.x) {
        float v = in[base + i];
        s += v;
        s2 += v * v;
    }
    __shared__ float sh0[256], sh1[256];
    sh0[threadIdx.x] = s;
    sh1[threadIdx.x] = s2;
    __syncthreads();
    for (int st = 128; st > 0; st >>= 1) {
        if (threadIdx.x < st) {
            sh0[threadIdx.x] += sh0[threadIdx.x + st];
            sh1[threadIdx.x] += sh1[threadIdx.x + st];
        }
        __syncthreads();
    }
    float mean = sh0[0] / n;
    float var = sh1[0] / n - mean * mean;
    float rstd = rsqrtf(var + 1e-5f);
    for (int i = threadIdx.x; i < n; i += blockDim.x) {
        int c = g * 8 + i / HW;
        float v = (in[base + i] - mean) * rstd * sc[c] + bi[c];
        if (relu) v = fmaxf(v, 0.f);
        out[base + i] = v;
    }
}

__global__ void addpool_kernel(const float* __restrict__ lat, const float* __restrict__ prev,
                               float* __restrict__ out, int H, int W) {
    int idx = blockIdx.x * blockDim.x + threadIdx.x;
    int total = BATCH * 256 * H * W;
    if (idx >= total) return;
    int x = idx % W;
    int y = (idx / W) % H;
    int bc = idx / (W * H);
    const float* p = prev + (long long)bc * 4 * H * W;
    int W2 = 2 * W;
    float v = 0.25f * (p[(2 * y) * W2 + 2 * x] + p[(2 * y) * W2 + 2 * x + 1] +
                       p[(2 * y + 1) * W2 + 2 * x] + p[(2 * y + 1) * W2 + 2 * x + 1]);
    out[idx] = lat[idx] + v;
}

// im2col old layout (level 3): col[b][ck][p]
__global__ void im2col_kernel(const float* __restrict__ in, float* __restrict__ col,
                              int H, int W) {
    int idx = blockIdx.x * blockDim.x + threadIdx.x;
    int HW = H * W;
    int total = BATCH * 2304 * HW;
    if (idx >= total) return;
    int p = idx % HW;
    int ck = (idx / HW) % 2304;
    int b = idx / (HW * 2304);
    int c = ck / 9, kk = ck % 9;
    int y = p / W + kk / 3 - 1;
    int x = p % W + kk % 3 - 1;
    float v = 0.f;
    if (y >= 0 && y < H && x >= 0 && x < W)
        v = in[((long long)b * 256 + c) * HW + y * W + x];
    col[idx] = v;
}

// im2col K-major: col[(b*HW+p)*2304 + ck]
__global__ void im2col_pc_kernel(const float* __restrict__ in, float* __restrict__ col,
                                 int H, int W) {
    int idx = blockIdx.x * blockDim.x + threadIdx.x;
    int HW = H * W;
    long long total = (long long)BATCH * HW * 2304;
    if (idx >= total) return;
    int ck = idx % 2304;
    int p = (idx / 2304) % HW;
    int b = idx / (2304 * HW);
    int c = ck / 9, kk = ck % 9;
    int y = p / W + kk / 3 - 1;
    int x = p % W + kk % 3 - 1;
    float v = 0.f;
    if (y >= 0 && y < H && x >= 0 && x < W)
        v = in[((long long)b * 256 + c) * HW + y * W + x];
    col[idx] = v;
}

__global__ void to_src_kernel(const float* __restrict__ ms, float* __restrict__ src,
                              int HW, int loff) {
    int idx = blockIdx.x * blockDim.x + threadIdx.x;
    int total = BATCH * HW * 256;
    if (idx >= total) return;
    int c = idx & 255;
    int p = (idx >> 8) % HW;
    int b = idx / (256 * HW);
    src[((long long)b * STOT + loff + p) * 256 + c] = ms[((long long)b * 256 + c) * HW + p];
}

__global__ void from_src_kernel(const float* __restrict__ src, float* __restrict__ out,
                                int HW, int loff) {
    int idx = blockIdx.x * blockDim.x + threadIdx.x;
    int total = BATCH * 256 * HW;
    if (idx >= total) return;
    int p = idx % HW;
    int c = (idx / HW) % 256;
    int b = idx / (HW * 256);
    out[idx] = src[((long long)b * STOT + loff + p) * 256 + c];
}

__global__ void pos_kernel(float* __restrict__ pos, float* __restrict__ refp) {
    int idx = blockIdx.x * blockDim.x + threadIdx.x;
    if (idx >= STOT * 256) return;
    int k = idx & 255;
    int s = idx >> 8;
    int H, W, p;
    if (s < 4096) { H = 64; W = 64; p = s; }
    else if (s < 5120) { H = 32; W = 32; p = s - 4096; }
    else if (s < 5376) { H = 16; W = 16; p = s - 5120; }
    else { H = 8; W = 8; p = s - 5376; }
    int y = p / W, x = p % W;
    float v;
    int feat;
    const float scale = 6.28318f;
    if (k < 128) { v = (y + 1.0f) / (H + 1e-6f) * scale; feat = k; }
    else { v = (x + 1.0f) / (W + 1e-6f) * scale; feat = k - 128; }
    float dim_t = powf(10000.0f, (2.0f * (feat / 2)) / 128.0f);
    float a = v / dim_t;
    pos[idx] = (feat & 1) ? cosf(a) : sinf(a);
    if (k == 0) {
        refp[s * 2 + 0] = (x + 0.5f) / W;
        refp[s * 2 + 1] = (y + 0.5f) / H;
    }
}

__global__ void addq_kernel(const float* __restrict__ src, const float* __restrict__ pos,
                            float* __restrict__ q) {
    int idx = blockIdx.x * blockDim.x + threadIdx.x;
    int total = BATCH * STOT * 256;
    if (idx >= total) return;
    q[idx] = src[idx] + pos[idx % (STOT * 256)];
}

__global__ void softmax16_kernel(float* __restrict__ aw) {
    int t = blockIdx.x * blockDim.x + threadIdx.x;
    int total = BATCH * STOT * NHEAD;
    if (t >= total) return;
    int bs = t / NHEAD, h = t % NHEAD;
    float* a = aw + (long long)bs * 128 + h * 16;
    float mx = -1e30f;
#pragma unroll
    for (int j = 0; j < 16; j++) mx = fmaxf(mx, a[j]);
    float e[16], sum = 0.f;
#pragma unroll
    for (int j = 0; j < 16; j++) { e[j] = __expf(a[j] - mx); sum += e[j]; }
    float inv = 1.0f / sum;
#pragma unroll
    for (int j = 0; j < 16; j++) a[j] = e[j] * inv;
}

__global__ void deform_kernel(const float* __restrict__ val, const float* __restrict__ off,
                              const float* __restrict__ aw, const float* __restrict__ refp,
                              float* __restrict__ out) {
    int gw = (blockIdx.x * blockDim.x + threadIdx.x) >> 5;
    int lane = threadIdx.x & 31;
    if (gw >= BATCH * STOT * NHEAD) return;
    int h = gw % NHEAD;
    int s = (gw / NHEAD) % STOT;
    int b = gw / (NHEAD * STOT);

    const int HWl[4] = {64, 32, 16, 8};
    const int loffs[4] = {0, 4096, 5120, 5376};
    float rx = refp[s * 2], ry = refp[s * 2 + 1];
    const float* offp = off + ((long long)(b * STOT + s)) * 256 + h * 32;
    const float* awp = aw + ((long long)(b * STOT + s)) * 128 + h * 16;
    float acc = 0.f;
#pragma unroll
    for (int l = 0; l < 4; l++) {
        int W = HWl[l], H = HWl[l], lo = loffs[l];
        float fW = (float)W, fH = (float)H;
#pragma unroll
        for (int p = 0; p < 4; p++) {
            float ox = offp[(l * 4 + p) * 2 + 0];
            float oy = offp[(l * 4 + p) * 2 + 1];
            float x = (rx + ox / fW) * fW - 0.5f;
            float y = (ry + oy / fH) * fH - 0.5f;
            float x0f = floorf(x), y0f = floorf(y);
            int x0 = (int)x0f, y0 = (int)y0f;
            float wx1 = x - x0f, wy1 = y - y0f;
            float wx0 = 1.f - wx1, wy0 = 1.f - wy1;
            float a = awp[l * 4 + p];
            float smp = 0.f;
#pragma unroll
            for (int cy = 0; cy < 2; cy++) {
#pragma unroll
                for (int cx = 0; cx < 2; cx++) {
                    int xi = x0 + cx, yi = y0 + cy;
                    if (xi >= 0 && xi < W && yi >= 0 && yi < H) {
                        float wgt = (cx ? wx1 : wx0) * (cy ? wy1 : wy0);
                        smp += wgt * val[((long long)(b * STOT + lo + yi * W + xi)) * 256 + h * 32 + lane];
                    }
                }
            }
            acc += a * smp;
        }
    }
    out[((long long)(b * STOT + s)) * 256 + h * 32 + lane] = acc;
}

__global__ void ln_res_kernel(float* __restrict__ src, const float* __restrict__ delta,
                              const float* __restrict__ sc, const float* __restrict__ bi) {
    long long base = (long long)blockIdx.x * 256;
    int t = threadIdx.x;
    float v = src[base + t] + delta[base + t];
    __shared__ float sh[256];
    sh[t] = v;
    __syncthreads();
    for (int s = 128; s > 0; s >>= 1) {
        if (t < s) sh[t] += sh[t + s];
        __syncthreads();
    }
    float mean = sh[0] * (1.0f / 256.0f);
    __syncthreads();
    float d = v - mean;
    sh[t] = d * d;
    __syncthreads();
    for (int s = 128; s > 0; s >>= 1) {
        if (t < s) sh[t] += sh[t + s];
        __syncthreads();
    }
    float var = sh[0] * (1.0f / 256.0f);
    src[base + t] = d * rsqrtf(var + 1e-5f) * sc[t] + bi[t];
}

// ---------------- host orchestration ----------------
extern "C" void kernel_launch(void* const* d_in, const int* in_sizes, int n_in,
                              void* d_out, int out_size) {
    const float* feat[4] = {(const float*)d_in[0], (const float*)d_in[1],
                            (const float*)d_in[2], (const float*)d_in[3]};
    const float* latw[4] = {(const float*)d_in[4], (const float*)d_in[5],
                            (const float*)d_in[6], (const float*)d_in[7]};
    const float* lat_gn_s = (const float*)d_in[8];
    const float* lat_gn_b = (const float*)d_in[9];
    const float* out_w = (const float*)d_in[10];
    const float* out_gn_s = (const float*)d_in[11];
    const float* out_gn_b = (const float*)d_in[12];
    const float* off_w = (const float*)d_in[13];
    const float* off_b = (const float*)d_in[14];
    const float* aw_w = (const float*)d_in[15];
    const float* aw_b = (const float*)d_in[16];
    const float* val_w = (const float*)d_in[17];
    const float* val_b = (const float*)d_in[18];
    const float* proj_w = (const float*)d_in[19];
    const float* proj_b = (const float*)d_in[20];
    const float* ffn1_w = (const float*)d_in[21];
    const float* ffn1_b = (const float*)d_in[22];
    const float* ffn2_w = (const float*)d_in[23];
    const float* ffn2_b = (const float*)d_in[24];
    const float* ln1_s = (const float*)d_in[25];
    const float* ln1_b = (const float*)d_in[26];
    const float* ln2_s = (const float*)d_in[27];
    const float* ln2_b = (const float*)d_in[28];
    const float* mask_w = (const float*)d_in[29];
    const float* mask_b = (const float*)d_in[30];

    float *lat, *o, *col, *ft, *wt, *ms, *src, *pos, *refp, *q, *val, *off, *aw, *attn, *tmp, *ffn;
    cudaGetSymbolAddress((void**)&lat, g_lat);
    cudaGetSymbolAddress((void**)&o, g_o);
    cudaGetSymbolAddress((void**)&col, g_col);
    cudaGetSymbolAddress((void**)&ft, g_ft);
    cudaGetSymbolAddress((void**)&wt, g_wt);
    cudaGetSymbolAddress((void**)&ms, g_ms);
    cudaGetSymbolAddress((void**)&src, g_src);
    cudaGetSymbolAddress((void**)&pos, g_pos);
    cudaGetSymbolAddress((void**)&refp, g_refpt);
    cudaGetSymbolAddress((void**)&q, g_q);
    cudaGetSymbolAddress((void**)&val, g_val);
    cudaGetSymbolAddress((void**)&off, g_off);
    cudaGetSymbolAddress((void**)&aw, g_aw);
    cudaGetSymbolAddress((void**)&attn, g_attn);
    cudaGetSymbolAddress((void**)&tmp, g_tmp);
    cudaGetSymbolAddress((void**)&ffn, g_ffn);

    // wt layout: val[0], off[65536], aw[131072 (128x256)], proj[163840],
    //            ffn1[229376 (2048x256)], ffn2[753664 (256x2048)]
    float* wt_val = wt;
    float* wt_off = wt + 65536;
    float* wt_aw = wt + 131072;
    float* wt_proj = wt + 163840;
    float* wt_f1 = wt + 229376;
    float* wt_f2 = wt + 753664;

    transw_kernel<<<(65536 + 255) / 256, 256>>>(val_w, wt_val, 256, 256);
    transw_kernel<<<(65536 + 255) / 256, 256>>>(off_w, wt_off, 256, 256);
    transw_kernel<<<(32768 + 255) / 256, 256>>>(aw_w, wt_aw, 256, 128);
    transw_kernel<<<(65536 + 255) / 256, 256>>>(proj_w, wt_proj, 256, 256);
    transw_kernel<<<(524288 + 255) / 256, 256>>>(ffn1_w, wt_f1, 256, 2048);
    transw_kernel<<<(524288 + 255) / 256, 256>>>(ffn2_w, wt_f2, 2048, 256);

    const int Hh[4] = {64, 32, 16, 8};
    const int HW[4] = {4096, 1024, 256, 64};
    const int Cin[4] = {256, 512, 1024, 2048};
    const int loff[4] = {0, 4096, 5120, 5376};
    long long msoff[4];
    msoff[0] = 0;
    for (int l = 1; l < 4; l++) msoff[l] = msoff[l - 1] + (long long)BATCH * 256 * HW[l - 1];

    // ---------- FPN ----------
    for (int l = 0; l < 4; l++) {
        if (l < 3) {
            int tot = BATCH * Cin[l] * HW[l];
            trfeat_kernel<<<(tot + 255) / 256, 256>>>(feat[l], ft, Cin[l], HW[l]);
            gx<<<dim3(HW[l] / 128, 2, BATCH), 256>>>(
                latw[l], ft, lat, Cin[l], Cin[l], Cin[l], HW[l],
                0LL, (long long)HW[l] * Cin[l], (long long)256 * HW[l], nullptr, 0, 0);
        } else {
            gemm64<<<dim3(1, 4, BATCH), 256>>>(latw[l], feat[l], lat, 256, HW[l], Cin[l],
                                               Cin[l], HW[l], HW[l],
                                               0LL, (long long)Cin[l] * HW[l],
                                               (long long)256 * HW[l], nullptr, 0, 0);
        }
        gn_kernel<<<dim3(32, BATCH), 256>>>(lat, lat, lat_gn_s + l * 256, lat_gn_b + l * 256,
                                            HW[l], 0);
        const float* oin = lat;
        if (l > 0) {
            int tot = BATCH * 256 * HW[l];
            addpool_kernel<<<(tot + 255) / 256, 256>>>(lat, ms + msoff[l - 1], o, Hh[l], Hh[l]);
            oin = o;
        }
        if (l < 3) {
            long long totc = (long long)BATCH * HW[l] * 2304;
            im2col_pc_kernel<<<(int)((totc + 255) / 256), 256>>>(oin, col, Hh[l], Hh[l]);
            gx<<<dim3(HW[l] / 128, 2, BATCH), 256>>>(
                out_w + (long long)l * 256 * 2304, col, lat, 2304, 2304, 2304, HW[l],
                0LL, (long long)HW[l] * 2304, (long long)256 * HW[l], nullptr, 0, 0);
        } else {
            int totc = BATCH * 2304 * HW[l];
            im2col_kernel<<<(totc + 255) / 256, 256>>>(oin, col, Hh[l], Hh[l]);
            gemm64<<<dim3(1, 4, BATCH), 256>>>(out_w + (long long)l * 256 * 2304, col, lat,
                                               256, HW[l], 2304, 2304, HW[l], HW[l],
                                               0LL, (long long)2304 * HW[l],
                                               (long long)256 * HW[l], nullptr, 0, 0);
        }
        gn_kernel<<<dim3(32, BATCH), 256>>>(lat, ms + msoff[l], out_gn_s + l * 256,
                                            out_gn_b + l * 256, HW[l], 1);
        int tots = BATCH * 256 * HW[l];
        to_src_kernel<<<(tots + 255) / 256, 256>>>(ms + msoff[l], src, HW[l], loff[l]);
    }

    // ---------- pos / ref ----------
    pos_kernel<<<(STOT * 256 + 255) / 256, 256>>>(pos, refp);

    // ---------- encoder layers ----------
    const int BS = BATCH * STOT;  // 10880 = 85 * 128
    for (int it = 0; it < NLAYER; it++) {
        int tot = BS * 256;
        addq_kernel<<<(tot + 255) / 256, 256>>>(src, pos, q);
        gx<<<dim3(2, 85), 256>>>(src, wt_val, val, 256, 256, 256, 256,
                                 0LL, 0LL, 0LL, val_b, 2, 0);
        gx<<<dim3(2, 85), 256>>>(q, wt_off, off, 256, 256, 256, 256,
                                 0LL, 0LL, 0LL, off_b, 2, 0);
        gx<<<dim3(1, 85), 256>>>(q, wt_aw, aw, 256, 256, 256, 128,
                                 0LL, 0LL, 0LL, aw_b, 2, 0);
        softmax16_kernel<<<(BS * NHEAD + 255) / 256, 256>>>(aw);
        deform_kernel<<<BS * NHEAD / 8, 256>>>(val, off, aw, refp, attn);
        gx<<<dim3(2, 85), 256>>>(attn, wt_proj, tmp, 256, 256, 256, 256,
                                 0LL, 0LL, 0LL, proj_b, 2, 0);
        ln_res_kernel<<<BS, 256>>>(src, tmp, ln1_s, ln1_b);
        gx<<<dim3(16, 85), 256>>>(src, wt_f1, ffn, 256, 256, 256, 2048,
                                  0LL, 0LL, 0LL, ffn1_b, 2, 1);
        gx<<<dim3(2, 85), 256>>>(ffn, wt_f2, tmp, 2048, 2048, 2048, 256,
                                 0LL, 0LL, 0LL, ffn2_b, 2, 0);
        ln_res_kernel<<<BS, 256>>>(src, tmp, ln2_s, ln2_b);
    }

    // ---------- outputs ----------
    float* outp = (float*)d_out;
    long long ooff[5];
    ooff[0] = 0;
    ooff[1] = ooff[0] + (long long)BATCH * 256 * 4096;
    ooff[2] = ooff[1] + (long long)BATCH * 256 * 4096;
    ooff[3] = ooff[2] + (long long)BATCH * 256 * 1024;
    ooff[4] = ooff[3] + (long long)BATCH * 256 * 256;
    for (int l = 0; l < 4; l++) {
        int tot = BATCH * 256 * HW[l];
        from_src_kernel<<<(tot + 255) / 256, 256>>>(src, outp + ooff[l + 1], HW[l], loff[l]);
    }
    // mask_feat: A = mask_w [256,256], B = src level-0 rows [4096,256] per batch
    gx<<<dim3(32, 2, BATCH), 256>>>(
        mask_w, src, outp, 256, 256, 256, 4096,
        0LL, (long long)STOT * 256, (long long)256 * 4096, mask_b, 1, 0);
}

// round 15
// speedup vs baseline: 1.1181x; 1.1181x over previous
#include <cuda_runtime.h>
#include <cuda_bf16.h>
#include <math.h>
#include <stdint.h>

#define BATCH 2
#define NHEAD 8
#define NLAYER 6
#define STOT 5440   // 4096+1024+256+64

// ---------------- scratch (static device globals; no runtime allocation) ----------------
__device__ float g_lat[BATCH * 256 * 4096];
__device__ float g_o[BATCH * 256 * 4096];
__device__ float g_col[BATCH * 2304 * 4096];
__device__ float g_ft[BATCH * 4096 * 256];
__device__ float g_wt[1310720];
__device__ float g_ms[BATCH * 256 * STOT];
__device__ float g_src[BATCH * STOT * 256];
__device__ float g_pos[STOT * 256];
__device__ float g_refpt[STOT * 2];
__device__ float g_q[BATCH * STOT * 256];
__device__ float g_val[BATCH * STOT * 256];
__device__ float g_off[BATCH * STOT * 256];
__device__ float g_aw[BATCH * STOT * 128];
__device__ float g_attn[BATCH * STOT * 256];
__device__ float g_tmp[BATCH * STOT * 256];
__device__ float g_ffn[BATCH * STOT * 2048];

// ---------------- helpers ----------------
__device__ __forceinline__ uint32_t smem_u32(const void* p) {
    uint32_t a;
    asm("{ .reg .u64 t; cvta.to.shared.u64 t, %1; cvt.u32.u64 %0, t; }" : "=r"(a) : "l"(p));
    return a;
}
__device__ __forceinline__ void ldm_x4(uint32_t& r0, uint32_t& r1, uint32_t& r2, uint32_t& r3,
                                       uint32_t addr) {
    asm volatile("ldmatrix.sync.aligned.m8n8.x4.shared.b16 {%0,%1,%2,%3}, [%4];"
                 : "=r"(r0), "=r"(r1), "=r"(r2), "=r"(r3) : "r"(addr));
}
__device__ __forceinline__ void mma_bf16(float* d, const uint32_t* a, const uint32_t* b) {
    asm volatile(
        "mma.sync.aligned.m16n8k16.row.col.f32.bf16.bf16.f32 "
        "{%0,%1,%2,%3}, {%4,%5,%6,%7}, {%8,%9}, {%0,%1,%2,%3};"
        : "+f"(d[0]), "+f"(d[1]), "+f"(d[2]), "+f"(d[3])
        : "r"(a[0]), "r"(a[1]), "r"(a[2]), "r"(a[3]), "r"(b[0]), "r"(b[1]));
}

#define PITCH 40                  // bf16 elems per smem row (32 data + 8 pad -> 80B pitch)
#define TILE_E (128 * PITCH)      // uint16 elems per 128-row tile plane

// ============ HMMA bf16x3 GEMM, NB-wide N tile ============
// C[M,N] = A[M,K] * B[N,K]^T (+bias)(+relu). fp32 GMEM, K-major rows.
// grid = (N/(128*NB), M/128, batch), 256 threads. K % 32 == 0.
// smem (dynamic): AsH | AsL | BsH (NB planes) | BsL (NB planes)
template<int NB>
__global__ __launch_bounds__(256)
void gx(const float* __restrict__ A, const float* __restrict__ B, float* __restrict__ C,
        int K, int lda, int ldb, int ldc,
        long long sA, long long sB, long long sC,
        const float* __restrict__ bias, int bias_mode, int relu) {
    extern __shared__ __align__(16) uint16_t sm[];
    A += (long long)blockIdx.z * sA;
    B += (long long)blockIdx.z * sB;
    C += (long long)blockIdx.z * sC;

    const int NCOL = 128 * NB;
    int tid = threadIdx.x;
    int lane = tid & 31, w = tid >> 5;
    int row0 = blockIdx.y * 128, col0 = blockIdx.x * NCOL;

    int lr = tid >> 3;          // 0..31
    int lk = (tid & 7) * 4;     // 0..28
    const float* Ap = A + (long long)(row0 + lr) * lda + lk;
    const float* Bp = B + (long long)(col0 + lr) * ldb + lk;

    // warp tile: 4 (M) x 2 (N) warps; warp = 32 (M) x (64*NB) (N)
    int m0 = (w >> 1) * 32;
    int n0 = (w & 1) * (64 * NB);

    uint16_t* AsH = sm;
    uint16_t* AsL = sm + TILE_E;
    uint16_t* BsH = sm + 2 * TILE_E;
    uint16_t* BsL = sm + (2 + NB) * TILE_E;
    uint32_t ah_base = smem_u32(AsH);
    uint32_t al_base = smem_u32(AsL);
    uint32_t bh_base = smem_u32(BsH);
    uint32_t bl_base = smem_u32(BsL);

    int lrow = ((lane >> 3) & 1) * 8 + (lane & 7);
    int lcol = ((lane >> 4) & 1) * 8;

    float acc[2][8 * NB][4];
#pragma unroll
    for (int i = 0; i < 2; i++)
#pragma unroll
        for (int j = 0; j < 8 * NB; j++)
#pragma unroll
            for (int q = 0; q < 4; q++) acc[i][j][q] = 0.f;

    int nst = K >> 5;
    float4 pa[4], pb[4 * NB];
#pragma unroll
    for (int i = 0; i < 4; i++)
        pa[i] = *(const float4*)(Ap + (long long)i * 32 * lda);
#pragma unroll
    for (int i = 0; i < 4 * NB; i++)
        pb[i] = *(const float4*)(Bp + (long long)i * 32 * ldb);

    for (int s = 0; s < nst; s++) {
        // ---- convert + split + store to smem ----
#pragma unroll
        for (int i = 0; i < 4; i++) {
            int o = (lr + i * 32) * PITCH + lk;
            float4 v = pa[i];
            __nv_bfloat162 h01 = __floats2bfloat162_rn(v.x, v.y);
            __nv_bfloat162 h23 = __floats2bfloat162_rn(v.z, v.w);
            __nv_bfloat162 l01 = __floats2bfloat162_rn(v.x - __bfloat162float(h01.x),
                                                       v.y - __bfloat162float(h01.y));
            __nv_bfloat162 l23 = __floats2bfloat162_rn(v.z - __bfloat162float(h23.x),
                                                       v.w - __bfloat162float(h23.y));
            *(uint32_t*)&AsH[o] = *(uint32_t*)&h01;
            *(uint32_t*)&AsH[o + 2] = *(uint32_t*)&h23;
            *(uint32_t*)&AsL[o] = *(uint32_t*)&l01;
            *(uint32_t*)&AsL[o + 2] = *(uint32_t*)&l23;
        }
#pragma unroll
        for (int i = 0; i < 4 * NB; i++) {
            int o = (lr + i * 32) * PITCH + lk;
            float4 v = pb[i];
            __nv_bfloat162 h01 = __floats2bfloat162_rn(v.x, v.y);
            __nv_bfloat162 h23 = __floats2bfloat162_rn(v.z, v.w);
            __nv_bfloat162 l01 = __floats2bfloat162_rn(v.x - __bfloat162float(h01.x),
                                                       v.y - __bfloat162float(h01.y));
            __nv_bfloat162 l23 = __floats2bfloat162_rn(v.z - __bfloat162float(h23.x),
                                                       v.w - __bfloat162float(h23.y));
            *(uint32_t*)&BsH[o] = *(uint32_t*)&h01;
            *(uint32_t*)&BsH[o + 2] = *(uint32_t*)&h23;
            *(uint32_t*)&BsL[o] = *(uint32_t*)&l01;
            *(uint32_t*)&BsL[o + 2] = *(uint32_t*)&l23;
        }
        __syncthreads();

        // prefetch next stage while computing this one
        if (s + 1 < nst) {
            int k0 = (s + 1) << 5;
#pragma unroll
            for (int i = 0; i < 4; i++)
                pa[i] = *(const float4*)(Ap + (long long)i * 32 * lda + k0);
#pragma unroll
            for (int i = 0; i < 4 * NB; i++)
                pb[i] = *(const float4*)(Bp + (long long)i * 32 * ldb + k0);
        }

        // ---- compute: 2 x k16 sub-steps ----
#pragma unroll
        for (int kk = 0; kk < 2; kk++) {
            int kc = kk * 16 + lcol;
            uint32_t aH[2][4], aL[2][4];
#pragma unroll
            for (int ma = 0; ma < 2; ma++) {
                uint32_t off = (uint32_t)((m0 + ma * 16 + lrow) * PITCH + kc) * 2;
                ldm_x4(aH[ma][0], aH[ma][1], aH[ma][2], aH[ma][3], ah_base + off);
                ldm_x4(aL[ma][0], aL[ma][1], aL[ma][2], aL[ma][3], al_base + off);
            }
#pragma unroll
            for (int ng = 0; ng < 4 * NB; ng++) {
                uint32_t off = (uint32_t)((n0 + ng * 16 + lrow) * PITCH + kc) * 2;
                uint32_t h0, h1, h2, h3, q0, q1, q2, q3;
                ldm_x4(h0, h1, h2, h3, bh_base + off);
                ldm_x4(q0, q1, q2, q3, bl_base + off);
                uint32_t bH0[2] = {h0, h2}, bH1[2] = {h1, h3};
                uint32_t bL0[2] = {q0, q2}, bL1[2] = {q1, q3};
#pragma unroll
                for (int ma = 0; ma < 2; ma++) {
                    mma_bf16(acc[ma][ng * 2], aH[ma], bH0);
                    mma_bf16(acc[ma][ng * 2], aH[ma], bL0);
                    mma_bf16(acc[ma][ng * 2], aL[ma], bH0);
                    mma_bf16(acc[ma][ng * 2 + 1], aH[ma], bH1);
                    mma_bf16(acc[ma][ng * 2 + 1], aH[ma], bL1);
                    mma_bf16(acc[ma][ng * 2 + 1], aL[ma], bH1);
                }
            }
        }
        __syncthreads();
    }

    // ---- epilogue ----
    int g = lane >> 2;
    int t2 = (lane & 3) * 2;
#pragma unroll
    for (int ma = 0; ma < 2; ma++) {
#pragma unroll
        for (int na = 0; na < 8 * NB; na++) {
            int mA = row0 + m0 + ma * 16 + g;
            int nA = col0 + n0 + na * 8 + t2;
            float b0 = 0.f, b1 = 0.f;
            if (bias_mode == 2) { b0 = bias[nA]; b1 = bias[nA + 1]; }
            float bmA = (bias_mode == 1) ? bias[mA] : 0.f;
            float bmB = (bias_mode == 1) ? bias[mA + 8] : 0.f;
            float2 o0, o1;
            o0.x = acc[ma][na][0] + bmA + b0;
            o0.y = acc[ma][na][1] + bmA + b1;
            o1.x = acc[ma][na][2] + bmB + b0;
            o1.y = acc[ma][na][3] + bmB + b1;
            if (relu) {
                o0.x = fmaxf(o0.x, 0.f); o0.y = fmaxf(o0.y, 0.f);
                o1.x = fmaxf(o1.x, 0.f); o1.y = fmaxf(o1.y, 0.f);
            }
            *(float2*)(C + (long long)mA * ldc + nA) = o0;
            *(float2*)(C + (long long)(mA + 8) * ldc + nA) = o1;
        }
    }
}

#define GX_SMEM1 (4 * TILE_E * 2)   // 40960 B
#define GX_SMEM2 (6 * TILE_E * 2)   // 61440 B

// ---------------- small fp32 GEMM (64x64x16), level 3 ----------------
__global__ void gemm64(const float* __restrict__ A, const float* __restrict__ B,
                       float* __restrict__ C,
                       int M, int N, int K, int lda, int ldb, int ldc,
                       long long sA, long long sB, long long sC,
                       const float* __restrict__ bias, int bias_mode, int relu) {
    A += (long long)blockIdx.z * sA;
    B += (long long)blockIdx.z * sB;
    C += (long long)blockIdx.z * sC;

    __shared__ float As[16][64];
    __shared__ float Bs[16][64];

    int tid = threadIdx.x;
    int tr = tid >> 4, tc = tid & 15;
    int row0 = blockIdx.y * 64, col0 = blockIdx.x * 64;

    int ar = tid >> 2;
    int ak = (tid & 3) * 4;
    int bk = tid >> 4;
    int bn = (tid & 15) * 4;

    float acc[4][4] = {};

    for (int k0 = 0; k0 < K; k0 += 16) {
        float4 a4 = *(const float4*)(A + (long long)(row0 + ar) * lda + k0 + ak);
        As[ak + 0][ar] = a4.x;
        As[ak + 1][ar] = a4.y;
        As[ak + 2][ar] = a4.z;
        As[ak + 3][ar] = a4.w;
        float4 b4 = *(const float4*)(B + (long long)(k0 + bk) * ldb + col0 + bn);
        *(float4*)&Bs[bk][bn] = b4;
        __syncthreads();

#pragma unroll
        for (int k = 0; k < 16; k++) {
            float4 av = *(const float4*)&As[k][tr * 4];
            float4 bv = *(const float4*)&Bs[k][tc * 4];
            float aa[4] = {av.x, av.y, av.z, av.w};
            float bb[4] = {bv.x, bv.y, bv.z, bv.w};
#pragma unroll
            for (int i = 0; i < 4; i++)
#pragma unroll
                for (int j = 0; j < 4; j++) acc[i][j] += aa[i] * bb[j];
        }
        __syncthreads();
    }

#pragma unroll
    for (int i = 0; i < 4; i++) {
        int m = row0 + tr * 4 + i;
        float bm = (bias_mode == 1) ? bias[m] : 0.f;
#pragma unroll
        for (int j = 0; j < 4; j++) {
            int n = col0 + tc * 4 + j;
            float v = acc[i][j] + bm + ((bias_mode == 2) ? bias[n] : 0.f);
            if (relu) v = fmaxf(v, 0.f);
            C[(long long)m * ldc + n] = v;
        }
    }
}

// ---------------- transposes ----------------
__global__ void transw_kernel(const float* __restrict__ in, float* __restrict__ out, int K, int N) {
    int idx = blockIdx.x * blockDim.x + threadIdx.x;
    if (idx >= K * N) return;
    int k = idx % K, n = idx / K;
    out[(long long)n * K + k] = in[(long long)k * N + n];
}

__global__ void trfeat_kernel(const float* __restrict__ in, float* __restrict__ out, int C, int HW) {
    int idx = blockIdx.x * blockDim.x + threadIdx.x;
    int total = BATCH * C * HW;
    if (idx >= total) return;
    int c = idx % C;
    int p = (idx / C) % HW;
    int b = idx / (C * HW);
    out[idx] = in[((long long)b * C + c) * HW + p];
}

// ---------------- GroupNorm ----------------
__global__ void gn_kernel(const float* __restrict__ in, float* __restrict__ out,
                          const float* __restrict__ sc, const float* __restrict__ bi,
                          int HW, int relu) {
    int b = blockIdx.y, g = blockIdx.x;
    long long base = ((long long)b * 256 + g * 8) * HW;
    int n = 8 * HW;
    float s = 0.f, s2 = 0.f;
    for (int i = threadIdx.x; i < n; i += blockDim.x) {
        float v = in[base + i];
        s += v;
        s2 += v * v;
    }
    __shared__ float sh0[256], sh1[256];
    sh0[threadIdx.x] = s;
    sh1[threadIdx.x] = s2;
    __syncthreads();
    for (int st = 128; st > 0; st >>= 1) {
        if (threadIdx.x < st) {
            sh0[threadIdx.x] += sh0[threadIdx.x + st];
            sh1[threadIdx.x] += sh1[threadIdx.x + st];
        }
        __syncthreads();
    }
    float mean = sh0[0] / n;
    float var = sh1[0] / n - mean * mean;
    float rstd = rsqrtf(var + 1e-5f);
    for (int i = threadIdx.x; i < n; i += blockDim.x) {
        int c = g * 8 + i / HW;
        float v = (in[base + i] - mean) * rstd * sc[c] + bi[c];
        if (relu) v = fmaxf(v, 0.f);
        out[base + i] = v;
    }
}

__global__ void addpool_kernel(const float* __restrict__ lat, const float* __restrict__ prev,
                               float* __restrict__ out, int H, int W) {
    int idx = blockIdx.x * blockDim.x + threadIdx.x;
    int total = BATCH * 256 * H * W;
    if (idx >= total) return;
    int x = idx % W;
    int y = (idx / W) % H;
    int bc = idx / (W * H);
    const float* p = prev + (long long)bc * 4 * H * W;
    int W2 = 2 * W;
    float v = 0.25f * (p[(2 * y) * W2 + 2 * x] + p[(2 * y) * W2 + 2 * x + 1] +
                       p[(2 * y + 1) * W2 + 2 * x] + p[(2 * y + 1) * W2 + 2 * x + 1]);
    out[idx] = lat[idx] + v;
}

// im2col old layout (level 3): col[b][ck][p]
__global__ void im2col_kernel(const float* __restrict__ in, float* __restrict__ col,
                              int H, int W) {
    int idx = blockIdx.x * blockDim.x + threadIdx.x;
    int HW = H * W;
    int total = BATCH * 2304 * HW;
    if (idx >= total) return;
    int p = idx % HW;
    int ck = (idx / HW) % 2304;
    int b = idx / (HW * 2304);
    int c = ck / 9, kk = ck % 9;
    int y = p / W + kk / 3 - 1;
    int x = p % W + kk % 3 - 1;
    float v = 0.f;
    if (y >= 0 && y < H && x >= 0 && x < W)
        v = in[((long long)b * 256 + c) * HW + y * W + x];
    col[idx] = v;
}

// im2col K-major: col[(b*HW+p)*2304 + ck]
__global__ void im2col_pc_kernel(const float* __restrict__ in, float* __restrict__ col,
                                 int H, int W) {
    int idx = blockIdx.x * blockDim.x + threadIdx.x;
    int HW = H * W;
    long long total = (long long)BATCH * HW * 2304;
    if (idx >= total) return;
    int ck = idx % 2304;
    int p = (idx / 2304) % HW;
    int b = idx / (2304 * HW);
    int c = ck / 9, kk = ck % 9;
    int y = p / W + kk / 3 - 1;
    int x = p % W + kk % 3 - 1;
    float v = 0.f;
    if (y >= 0 && y < H && x >= 0 && x < W)
        v = in[((long long)b * 256 + c) * HW + y * W + x];
    col[idx] = v;
}

__global__ void to_src_kernel(const float* __restrict__ ms, float* __restrict__ src,
                              int HW, int loff) {
    int idx = blockIdx.x * blockDim.x + threadIdx.x;
    int total = BATCH * HW * 256;
    if (idx >= total) return;
    int c = idx & 255;
    int p = (idx >> 8) % HW;
    int b = idx / (256 * HW);
    src[((long long)b * STOT + loff + p) * 256 + c] = ms[((long long)b * 256 + c) * HW + p];
}

__global__ void from_src_kernel(const float* __restrict__ src, float* __restrict__ out,
                                int HW, int loff) {
    int idx = blockIdx.x * blockDim.x + threadIdx.x;
    int total = BATCH * 256 * HW;
    if (idx >= total) return;
    int p = idx % HW;
    int c = (idx / HW) % 256;
    int b = idx / (HW * 256);
    out[idx] = src[((long long)b * STOT + loff + p) * 256 + c];
}

__global__ void pos_kernel(float* __restrict__ pos, float* __restrict__ refp) {
    int idx = blockIdx.x * blockDim.x + threadIdx.x;
    if (idx >= STOT * 256) return;
    int k = idx & 255;
    int s = idx >> 8;
    int H, W, p;
    if (s < 4096) { H = 64; W = 64; p = s; }
    else if (s < 5120) { H = 32; W = 32; p = s - 4096; }
    else if (s < 5376) { H = 16; W = 16; p = s - 5120; }
    else { H = 8; W = 8; p = s - 5376; }
    int y = p / W, x = p % W;
    float v;
    int feat;
    const float scale = 6.28318f;
    if (k < 128) { v = (y + 1.0f) / (H + 1e-6f) * scale; feat = k; }
    else { v = (x + 1.0f) / (W + 1e-6f) * scale; feat = k - 128; }
    float dim_t = powf(10000.0f, (2.0f * (feat / 2)) / 128.0f);
    float a = v / dim_t;
    pos[idx] = (feat & 1) ? cosf(a) : sinf(a);
    if (k == 0) {
        refp[s * 2 + 0] = (x + 0.5f) / W;
        refp[s * 2 + 1] = (y + 0.5f) / H;
    }
}

__global__ void addq_kernel(const float* __restrict__ src, const float* __restrict__ pos,
                            float* __restrict__ q) {
    int idx = blockIdx.x * blockDim.x + threadIdx.x;
    int total = BATCH * STOT * 256;
    if (idx >= total) return;
    q[idx] = src[idx] + pos[idx % (STOT * 256)];
}

__global__ void softmax16_kernel(float* __restrict__ aw) {
    int t = blockIdx.x * blockDim.x + threadIdx.x;
    int total = BATCH * STOT * NHEAD;
    if (t >= total) return;
    int bs = t / NHEAD, h = t % NHEAD;
    float* a = aw + (long long)bs * 128 + h * 16;
    float mx = -1e30f;
#pragma unroll
    for (int j = 0; j < 16; j++) mx = fmaxf(mx, a[j]);
    float e[16], sum = 0.f;
#pragma unroll
    for (int j = 0; j < 16; j++) { e[j] = __expf(a[j] - mx); sum += e[j]; }
    float inv = 1.0f / sum;
#pragma unroll
    for (int j = 0; j < 16; j++) a[j] = e[j] * inv;
}

__global__ void deform_kernel(const float* __restrict__ val, const float* __restrict__ off,
                              const float* __restrict__ aw, const float* __restrict__ refp,
                              float* __restrict__ out) {
    int gw = (blockIdx.x * blockDim.x + threadIdx.x) >> 5;
    int lane = threadIdx.x & 31;
    if (gw >= BATCH * STOT * NHEAD) return;
    int h = gw % NHEAD;
    int s = (gw / NHEAD) % STOT;
    int b = gw / (NHEAD * STOT);

    const int HWl[4] = {64, 32, 16, 8};
    const int loffs[4] = {0, 4096, 5120, 5376};
    float rx = refp[s * 2], ry = refp[s * 2 + 1];
    const float* offp = off + ((long long)(b * STOT + s)) * 256 + h * 32;
    const float* awp = aw + ((long long)(b * STOT + s)) * 128 + h * 16;
    float acc = 0.f;
#pragma unroll
    for (int l = 0; l < 4; l++) {
        int W = HWl[l], H = HWl[l], lo = loffs[l];
        float fW = (float)W, fH = (float)H;
#pragma unroll
        for (int p = 0; p < 4; p++) {
            float ox = offp[(l * 4 + p) * 2 + 0];
            float oy = offp[(l * 4 + p) * 2 + 1];
            float x = (rx + ox / fW) * fW - 0.5f;
            float y = (ry + oy / fH) * fH - 0.5f;
            float x0f = floorf(x), y0f = floorf(y);
            int x0 = (int)x0f, y0 = (int)y0f;
            float wx1 = x - x0f, wy1 = y - y0f;
            float wx0 = 1.f - wx1, wy0 = 1.f - wy1;
            float a = awp[l * 4 + p];
            float smp = 0.f;
#pragma unroll
            for (int cy = 0; cy < 2; cy++) {
#pragma unroll
                for (int cx = 0; cx < 2; cx++) {
                    int xi = x0 + cx, yi = y0 + cy;
                    if (xi >= 0 && xi < W && yi >= 0 && yi < H) {
                        float wgt = (cx ? wx1 : wx0) * (cy ? wy1 : wy0);
                        smp += wgt * val[((long long)(b * STOT + lo + yi * W + xi)) * 256 + h * 32 + lane];
                    }
                }
            }
            acc += a * smp;
        }
    }
    out[((long long)(b * STOT + s)) * 256 + h * 32 + lane] = acc;
}

__global__ void ln_res_kernel(float* __restrict__ src, const float* __restrict__ delta,
                              const float* __restrict__ sc, const float* __restrict__ bi) {
    long long base = (long long)blockIdx.x * 256;
    int t = threadIdx.x;
    float v = src[base + t] + delta[base + t];
    __shared__ float sh[256];
    sh[t] = v;
    __syncthreads();
    for (int s = 128; s > 0; s >>= 1) {
        if (t < s) sh[t] += sh[t + s];
        __syncthreads();
    }
    float mean = sh[0] * (1.0f / 256.0f);
    __syncthreads();
    float d = v - mean;
    sh[t] = d * d;
    __syncthreads();
    for (int s = 128; s > 0; s >>= 1) {
        if (t < s) sh[t] += sh[t + s];
        __syncthreads();
    }
    float var = sh[0] * (1.0f / 256.0f);
    src[base + t] = d * rsqrtf(var + 1e-5f) * sc[t] + bi[t];
}

// ---------------- host orchestration ----------------
extern "C" void kernel_launch(void* const* d_in, const int* in_sizes, int n_in,
                              void* d_out, int out_size) {
    const float* feat[4] = {(const float*)d_in[0], (const float*)d_in[1],
                            (const float*)d_in[2], (const float*)d_in[3]};
    const float* latw[4] = {(const float*)d_in[4], (const float*)d_in[5],
                            (const float*)d_in[6], (const float*)d_in[7]};
    const float* lat_gn_s = (const float*)d_in[8];
    const float* lat_gn_b = (const float*)d_in[9];
    const float* out_w = (const float*)d_in[10];
    const float* out_gn_s = (const float*)d_in[11];
    const float* out_gn_b = (const float*)d_in[12];
    const float* off_w = (const float*)d_in[13];
    const float* off_b = (const float*)d_in[14];
    const float* aw_w = (const float*)d_in[15];
    const float* aw_b = (const float*)d_in[16];
    const float* val_w = (const float*)d_in[17];
    const float* val_b = (const float*)d_in[18];
    const float* proj_w = (const float*)d_in[19];
    const float* proj_b = (const float*)d_in[20];
    const float* ffn1_w = (const float*)d_in[21];
    const float* ffn1_b = (const float*)d_in[22];
    const float* ffn2_w = (const float*)d_in[23];
    const float* ffn2_b = (const float*)d_in[24];
    const float* ln1_s = (const float*)d_in[25];
    const float* ln1_b = (const float*)d_in[26];
    const float* ln2_s = (const float*)d_in[27];
    const float* ln2_b = (const float*)d_in[28];
    const float* mask_w = (const float*)d_in[29];
    const float* mask_b = (const float*)d_in[30];

    static int smem_set = 0;
    if (!smem_set) {
        cudaFuncSetAttribute(gx<1>, cudaFuncAttributeMaxDynamicSharedMemorySize, GX_SMEM1);
        cudaFuncSetAttribute(gx<2>, cudaFuncAttributeMaxDynamicSharedMemorySize, GX_SMEM2);
        smem_set = 1;
    }

    float *lat, *o, *col, *ft, *wt, *ms, *src, *pos, *refp, *q, *val, *off, *aw, *attn, *tmp, *ffn;
    cudaGetSymbolAddress((void**)&lat, g_lat);
    cudaGetSymbolAddress((void**)&o, g_o);
    cudaGetSymbolAddress((void**)&col, g_col);
    cudaGetSymbolAddress((void**)&ft, g_ft);
    cudaGetSymbolAddress((void**)&wt, g_wt);
    cudaGetSymbolAddress((void**)&ms, g_ms);
    cudaGetSymbolAddress((void**)&src, g_src);
    cudaGetSymbolAddress((void**)&pos, g_pos);
    cudaGetSymbolAddress((void**)&refp, g_refpt);
    cudaGetSymbolAddress((void**)&q, g_q);
    cudaGetSymbolAddress((void**)&val, g_val);
    cudaGetSymbolAddress((void**)&off, g_off);
    cudaGetSymbolAddress((void**)&aw, g_aw);
    cudaGetSymbolAddress((void**)&attn, g_attn);
    cudaGetSymbolAddress((void**)&tmp, g_tmp);
    cudaGetSymbolAddress((void**)&ffn, g_ffn);

    // wt layout: val[0], off[65536], aw[131072 (128x256)], proj[163840],
    //            ffn1[229376 (2048x256)], ffn2[753664 (256x2048)]
    float* wt_val = wt;
    float* wt_off = wt + 65536;
    float* wt_aw = wt + 131072;
    float* wt_proj = wt + 163840;
    float* wt_f1 = wt + 229376;
    float* wt_f2 = wt + 753664;

    transw_kernel<<<(65536 + 255) / 256, 256>>>(val_w, wt_val, 256, 256);
    transw_kernel<<<(65536 + 255) / 256, 256>>>(off_w, wt_off, 256, 256);
    transw_kernel<<<(32768 + 255) / 256, 256>>>(aw_w, wt_aw, 256, 128);
    transw_kernel<<<(65536 + 255) / 256, 256>>>(proj_w, wt_proj, 256, 256);
    transw_kernel<<<(524288 + 255) / 256, 256>>>(ffn1_w, wt_f1, 256, 2048);
    transw_kernel<<<(524288 + 255) / 256, 256>>>(ffn2_w, wt_f2, 2048, 256);

    const int Hh[4] = {64, 32, 16, 8};
    const int HW[4] = {4096, 1024, 256, 64};
    const int Cin[4] = {256, 512, 1024, 2048};
    const int loff[4] = {0, 4096, 5120, 5376};
    long long msoff[4];
    msoff[0] = 0;
    for (int l = 1; l < 4; l++) msoff[l] = msoff[l - 1] + (long long)BATCH * 256 * HW[l - 1];

    // ---------- FPN ----------
    for (int l = 0; l < 4; l++) {
        if (l < 3) {
            int tot = BATCH * Cin[l] * HW[l];
            trfeat_kernel<<<(tot + 255) / 256, 256>>>(feat[l], ft, Cin[l], HW[l]);
            gx<2><<<dim3(HW[l] / 256, 2, BATCH), 256, GX_SMEM2>>>(
                latw[l], ft, lat, Cin[l], Cin[l], Cin[l], HW[l],
                0LL, (long long)HW[l] * Cin[l], (long long)256 * HW[l], nullptr, 0, 0);
        } else {
            gemm64<<<dim3(1, 4, BATCH), 256>>>(latw[l], feat[l], lat, 256, HW[l], Cin[l],
                                               Cin[l], HW[l], HW[l],
                                               0LL, (long long)Cin[l] * HW[l],
                                               (long long)256 * HW[l], nullptr, 0, 0);
        }
        gn_kernel<<<dim3(32, BATCH), 256>>>(lat, lat, lat_gn_s + l * 256, lat_gn_b + l * 256,
                                            HW[l], 0);
        const float* oin = lat;
        if (l > 0) {
            int tot = BATCH * 256 * HW[l];
            addpool_kernel<<<(tot + 255) / 256, 256>>>(lat, ms + msoff[l - 1], o, Hh[l], Hh[l]);
            oin = o;
        }
        if (l < 3) {
            long long totc = (long long)BATCH * HW[l] * 2304;
            im2col_pc_kernel<<<(int)((totc + 255) / 256), 256>>>(oin, col, Hh[l], Hh[l]);
            gx<2><<<dim3(HW[l] / 256, 2, BATCH), 256, GX_SMEM2>>>(
                out_w + (long long)l * 256 * 2304, col, lat, 2304, 2304, 2304, HW[l],
                0LL, (long long)HW[l] * 2304, (long long)256 * HW[l], nullptr, 0, 0);
        } else {
            int totc = BATCH * 2304 * HW[l];
            im2col_kernel<<<(totc + 255) / 256, 256>>>(oin, col, Hh[l], Hh[l]);
            gemm64<<<dim3(1, 4, BATCH), 256>>>(out_w + (long long)l * 256 * 2304, col, lat,
                                               256, HW[l], 2304, 2304, HW[l], HW[l],
                                               0LL, (long long)2304 * HW[l],
                                               (long long)256 * HW[l], nullptr, 0, 0);
        }
        gn_kernel<<<dim3(32, BATCH), 256>>>(lat, ms + msoff[l], out_gn_s + l * 256,
                                            out_gn_b + l * 256, HW[l], 1);
        int tots = BATCH * 256 * HW[l];
        to_src_kernel<<<(tots + 255) / 256, 256>>>(ms + msoff[l], src, HW[l], loff[l]);
    }

    // ---------- pos / ref ----------
    pos_kernel<<<(STOT * 256 + 255) / 256, 256>>>(pos, refp);

    // ---------- encoder layers ----------
    const int BS = BATCH * STOT;  // 10880 = 85 * 128
    for (int it = 0; it < NLAYER; it++) {
        int tot = BS * 256;
        addq_kernel<<<(tot + 255) / 256, 256>>>(src, pos, q);
        gx<2><<<dim3(1, 85), 256, GX_SMEM2>>>(src, wt_val, val, 256, 256, 256, 256,
                                              0LL, 0LL, 0LL, val_b, 2, 0);
        gx<2><<<dim3(1, 85), 256, GX_SMEM2>>>(q, wt_off, off, 256, 256, 256, 256,
                                              0LL, 0LL, 0LL, off_b, 2, 0);
        gx<1><<<dim3(1, 85), 256, GX_SMEM1>>>(q, wt_aw, aw, 256, 256, 256, 128,
                                              0LL, 0LL, 0LL, aw_b, 2, 0);
        softmax16_kernel<<<(BS * NHEAD + 255) / 256, 256>>>(aw);
        deform_kernel<<<BS * NHEAD / 8, 256>>>(val, off, aw, refp, attn);
        gx<2><<<dim3(1, 85), 256, GX_SMEM2>>>(attn, wt_proj, tmp, 256, 256, 256, 256,
                                              0LL, 0LL, 0LL, proj_b, 2, 0);
        ln_res_kernel<<<BS, 256>>>(src, tmp, ln1_s, ln1_b);
        gx<2><<<dim3(8, 85), 256, GX_SMEM2>>>(src, wt_f1, ffn, 256, 256, 256, 2048,
                                              0LL, 0LL, 0LL, ffn1_b, 2, 1);
        gx<2><<<dim3(1, 85), 256, GX_SMEM2>>>(ffn, wt_f2, tmp, 2048, 2048, 2048, 256,
                                              0LL, 0LL, 0LL, ffn2_b, 2, 0);
        ln_res_kernel<<<BS, 256>>>(src, tmp, ln2_s, ln2_b);
    }

    // ---------- outputs ----------
    float* outp = (float*)d_out;
    long long ooff[5];
    ooff[0] = 0;
    ooff[1] = ooff[0] + (long long)BATCH * 256 * 4096;
    ooff[2] = ooff[1] + (long long)BATCH * 256 * 4096;
    ooff[3] = ooff[2] + (long long)BATCH * 256 * 1024;
    ooff[4] = ooff[3] + (long long)BATCH * 256 * 256;
    for (int l = 0; l < 4; l++) {
        int tot = BATCH * 256 * HW[l];
        from_src_kernel<<<(tot + 255) / 256, 256>>>(src, outp + ooff[l + 1], HW[l], loff[l]);
    }
    // mask_feat: A = mask_w [256,256], B = src level-0 rows [4096,256] per batch
    gx<2><<<dim3(16, 2, BATCH), 256, GX_SMEM2>>>(
        mask_w, src, outp, 256, 256, 256, 4096,
        0LL, (long long)STOT * 256, (long long)256 * 4096, mask_b, 1, 0);
}

// round 16
// speedup vs baseline: 1.1431x; 1.0223x over previous
#include <cuda_runtime.h>
#include <cuda_bf16.h>
#include <math.h>
#include <stdint.h>

#define BATCH 2
#define NHEAD 8
#define NLAYER 6
#define STOT 5440   // 4096+1024+256+64

// ---------------- scratch (static device globals; no runtime allocation) ----------------
__device__ float g_lat[BATCH * 256 * 4096];
__device__ float g_o[BATCH * 256 * 4096];
__device__ float g_col[BATCH * 2304 * 4096];
__device__ float g_ft[BATCH * 4096 * 256];
__device__ float g_wt[1310720];
__device__ float g_ms[BATCH * 256 * STOT];
__device__ float g_src[BATCH * STOT * 256];
__device__ float g_pos[STOT * 256];
__device__ float g_refpt[STOT * 2];
__device__ float g_q[BATCH * STOT * 256];
__device__ float g_val[BATCH * STOT * 256];
__device__ float g_off[BATCH * STOT * 256];
__device__ float g_aw[BATCH * STOT * 128];
__device__ float g_attn[BATCH * STOT * 256];
__device__ float g_tmp[BATCH * STOT * 256];
__device__ float g_ffn[BATCH * STOT * 2048];

// ---------------- helpers ----------------
__device__ __forceinline__ uint32_t smem_u32(const void* p) {
    uint32_t a;
    asm("{ .reg .u64 t; cvta.to.shared.u64 t, %1; cvt.u32.u64 %0, t; }" : "=r"(a) : "l"(p));
    return a;
}
__device__ __forceinline__ void ldm_x4(uint32_t& r0, uint32_t& r1, uint32_t& r2, uint32_t& r3,
                                       uint32_t addr) {
    asm volatile("ldmatrix.sync.aligned.m8n8.x4.shared.b16 {%0,%1,%2,%3}, [%4];"
                 : "=r"(r0), "=r"(r1), "=r"(r2), "=r"(r3) : "r"(addr));
}
__device__ __forceinline__ void mma_bf16(float* d, const uint32_t* a, const uint32_t* b) {
    asm volatile(
        "mma.sync.aligned.m16n8k16.row.col.f32.bf16.bf16.f32 "
        "{%0,%1,%2,%3}, {%4,%5,%6,%7}, {%8,%9}, {%0,%1,%2,%3};"
        : "+f"(d[0]), "+f"(d[1]), "+f"(d[2]), "+f"(d[3])
        : "r"(a[0]), "r"(a[1]), "r"(a[2]), "r"(a[3]), "r"(b[0]), "r"(b[1]));
}

// ============ HMMA bf16x3 GEMM (record-holder R7 core) ============
// C[M,N] = A[M,K] * B[N,K]^T (+bias)(+relu). A,B fp32 in GMEM, K-major rows.
// grid = (N/128, M/128, batch), 256 threads. K % 32 == 0.
#define PITCH 40   // bf16 elems per smem row (32 data + 8 pad -> 80B pitch, ldmatrix conflict-free)

__global__ __launch_bounds__(256)
void gx(const float* __restrict__ A, const float* __restrict__ B, float* __restrict__ C,
        int K, int lda, int ldb, int ldc,
        long long sA, long long sB, long long sC,
        const float* __restrict__ bias, int bias_mode, int relu) {
    A += (long long)blockIdx.z * sA;
    B += (long long)blockIdx.z * sB;
    C += (long long)blockIdx.z * sC;

    __shared__ __align__(16) uint16_t AsH[128][PITCH];
    __shared__ __align__(16) uint16_t AsL[128][PITCH];
    __shared__ __align__(16) uint16_t BsH[128][PITCH];
    __shared__ __align__(16) uint16_t BsL[128][PITCH];

    int tid = threadIdx.x;
    int lane = tid & 31, w = tid >> 5;
    int row0 = blockIdx.y * 128, col0 = blockIdx.x * 128;

    // loader mapping: 8 lanes cover one row's 32 floats
    int lr = tid >> 3;          // 0..31
    int lk = (tid & 7) * 4;     // 0,4,...,28
    const float* Ap = A + (long long)(row0 + lr) * lda + lk;
    const float* Bp = B + (long long)(col0 + lr) * ldb + lk;

    // warp tile: 4 (M) x 2 (N) warps; warp = 32 (M) x 64 (N)
    int m0 = (w >> 1) * 32;
    int n0 = (w & 1) * 64;

    uint32_t ah_base = smem_u32(&AsH[0][0]);
    uint32_t al_base = smem_u32(&AsL[0][0]);
    uint32_t bh_base = smem_u32(&BsH[0][0]);
    uint32_t bl_base = smem_u32(&BsL[0][0]);

    // ldmatrix per-thread row/col offsets
    int lrow = ((lane >> 3) & 1) * 8 + (lane & 7);
    int lcol = ((lane >> 4) & 1) * 8;

    float acc[2][8][4];
#pragma unroll
    for (int i = 0; i < 2; i++)
#pragma unroll
        for (int j = 0; j < 8; j++)
#pragma unroll
            for (int q = 0; q < 4; q++) acc[i][j][q] = 0.f;

    int nst = K >> 5;
    float4 pa[4], pb[4];
#pragma unroll
    for (int i = 0; i < 4; i++) {
        pa[i] = *(const float4*)(Ap + (long long)i * 32 * lda);
        pb[i] = *(const float4*)(Bp + (long long)i * 32 * ldb);
    }

    for (int s = 0; s < nst; s++) {
        // ---- convert + split + store to smem ----
#pragma unroll
        for (int i = 0; i < 4; i++) {
            int r = lr + i * 32;
            float4 v = pa[i];
            __nv_bfloat162 h01 = __floats2bfloat162_rn(v.x, v.y);
            __nv_bfloat162 h23 = __floats2bfloat162_rn(v.z, v.w);
            __nv_bfloat162 l01 = __floats2bfloat162_rn(v.x - __bfloat162float(h01.x),
                                                       v.y - __bfloat162float(h01.y));
            __nv_bfloat162 l23 = __floats2bfloat162_rn(v.z - __bfloat162float(h23.x),
                                                       v.w - __bfloat162float(h23.y));
            *(uint32_t*)&AsH[r][lk] = *(uint32_t*)&h01;
            *(uint32_t*)&AsH[r][lk + 2] = *(uint32_t*)&h23;
            *(uint32_t*)&AsL[r][lk] = *(uint32_t*)&l01;
            *(uint32_t*)&AsL[r][lk + 2] = *(uint32_t*)&l23;

            v = pb[i];
            h01 = __floats2bfloat162_rn(v.x, v.y);
            h23 = __floats2bfloat162_rn(v.z, v.w);
            l01 = __floats2bfloat162_rn(v.x - __bfloat162float(h01.x),
                                        v.y - __bfloat162float(h01.y));
            l23 = __floats2bfloat162_rn(v.z - __bfloat162float(h23.x),
                                        v.w - __bfloat162float(h23.y));
            *(uint32_t*)&BsH[r][lk] = *(uint32_t*)&h01;
            *(uint32_t*)&BsH[r][lk + 2] = *(uint32_t*)&h23;
            *(uint32_t*)&BsL[r][lk] = *(uint32_t*)&l01;
            *(uint32_t*)&BsL[r][lk + 2] = *(uint32_t*)&l23;
        }
        __syncthreads();

        // prefetch next stage while computing this one
        if (s + 1 < nst) {
            int k0 = (s + 1) << 5;
#pragma unroll
            for (int i = 0; i < 4; i++) {
                pa[i] = *(const float4*)(Ap + (long long)i * 32 * lda + k0);
                pb[i] = *(const float4*)(Bp + (long long)i * 32 * ldb + k0);
            }
        }

        // ---- compute: 2 x k16 sub-steps ----
#pragma unroll
        for (int kk = 0; kk < 2; kk++) {
            int kc = kk * 16 + lcol;
            uint32_t aH[2][4], aL[2][4], bH[8][2], bL[8][2];
#pragma unroll
            for (int ma = 0; ma < 2; ma++) {
                uint32_t off = (uint32_t)((m0 + ma * 16 + lrow) * PITCH + kc) * 2;
                ldm_x4(aH[ma][0], aH[ma][1], aH[ma][2], aH[ma][3], ah_base + off);
                ldm_x4(aL[ma][0], aL[ma][1], aL[ma][2], aL[ma][3], al_base + off);
            }
#pragma unroll
            for (int ng = 0; ng < 4; ng++) {
                uint32_t off = (uint32_t)((n0 + ng * 16 + lrow) * PITCH + kc) * 2;
                uint32_t r0, r1, r2, r3;
                ldm_x4(r0, r1, r2, r3, bh_base + off);
                bH[ng * 2][0] = r0; bH[ng * 2][1] = r2;
                bH[ng * 2 + 1][0] = r1; bH[ng * 2 + 1][1] = r3;
                ldm_x4(r0, r1, r2, r3, bl_base + off);
                bL[ng * 2][0] = r0; bL[ng * 2][1] = r2;
                bL[ng * 2 + 1][0] = r1; bL[ng * 2 + 1][1] = r3;
            }
#pragma unroll
            for (int ma = 0; ma < 2; ma++)
#pragma unroll
                for (int na = 0; na < 8; na++) {
                    mma_bf16(acc[ma][na], aH[ma], bH[na]);
                    mma_bf16(acc[ma][na], aH[ma], bL[na]);
                    mma_bf16(acc[ma][na], aL[ma], bH[na]);
                }
        }
        __syncthreads();
    }

    // ---- epilogue ----
    int g = lane >> 2;
    int t2 = (lane & 3) * 2;
#pragma unroll
    for (int ma = 0; ma < 2; ma++) {
#pragma unroll
        for (int na = 0; na < 8; na++) {
            int mA = row0 + m0 + ma * 16 + g;
            int nA = col0 + n0 + na * 8 + t2;
            float b0 = 0.f, b1 = 0.f;
            if (bias_mode == 2) { b0 = bias[nA]; b1 = bias[nA + 1]; }
            float bmA = (bias_mode == 1) ? bias[mA] : 0.f;
            float bmB = (bias_mode == 1) ? bias[mA + 8] : 0.f;
            float2 o0, o1;
            o0.x = acc[ma][na][0] + bmA + b0;
            o0.y = acc[ma][na][1] + bmA + b1;
            o1.x = acc[ma][na][2] + bmB + b0;
            o1.y = acc[ma][na][3] + bmB + b1;
            if (relu) {
                o0.x = fmaxf(o0.x, 0.f); o0.y = fmaxf(o0.y, 0.f);
                o1.x = fmaxf(o1.x, 0.f); o1.y = fmaxf(o1.y, 0.f);
            }
            *(float2*)(C + (long long)mA * ldc + nA) = o0;
            *(float2*)(C + (long long)(mA + 8) * ldc + nA) = o1;
        }
    }
}

// ---------------- small fp32 GEMM (64x64x16), level 3 ----------------
__global__ void gemm64(const float* __restrict__ A, const float* __restrict__ B,
                       float* __restrict__ C,
                       int M, int N, int K, int lda, int ldb, int ldc,
                       long long sA, long long sB, long long sC,
                       const float* __restrict__ bias, int bias_mode, int relu) {
    A += (long long)blockIdx.z * sA;
    B += (long long)blockIdx.z * sB;
    C += (long long)blockIdx.z * sC;

    __shared__ float As[16][64];
    __shared__ float Bs[16][64];

    int tid = threadIdx.x;
    int tr = tid >> 4, tc = tid & 15;
    int row0 = blockIdx.y * 64, col0 = blockIdx.x * 64;

    int ar = tid >> 2;
    int ak = (tid & 3) * 4;
    int bk = tid >> 4;
    int bn = (tid & 15) * 4;

    float acc[4][4] = {};

    for (int k0 = 0; k0 < K; k0 += 16) {
        float4 a4 = *(const float4*)(A + (long long)(row0 + ar) * lda + k0 + ak);
        As[ak + 0][ar] = a4.x;
        As[ak + 1][ar] = a4.y;
        As[ak + 2][ar] = a4.z;
        As[ak + 3][ar] = a4.w;
        float4 b4 = *(const float4*)(B + (long long)(k0 + bk) * ldb + col0 + bn);
        *(float4*)&Bs[bk][bn] = b4;
        __syncthreads();

#pragma unroll
        for (int k = 0; k < 16; k++) {
            float4 av = *(const float4*)&As[k][tr * 4];
            float4 bv = *(const float4*)&Bs[k][tc * 4];
            float aa[4] = {av.x, av.y, av.z, av.w};
            float bb[4] = {bv.x, bv.y, bv.z, bv.w};
#pragma unroll
            for (int i = 0; i < 4; i++)
#pragma unroll
                for (int j = 0; j < 4; j++) acc[i][j] += aa[i] * bb[j];
        }
        __syncthreads();
    }

#pragma unroll
    for (int i = 0; i < 4; i++) {
        int m = row0 + tr * 4 + i;
        float bm = (bias_mode == 1) ? bias[m] : 0.f;
#pragma unroll
        for (int j = 0; j < 4; j++) {
            int n = col0 + tc * 4 + j;
            float v = acc[i][j] + bm + ((bias_mode == 2) ? bias[n] : 0.f);
            if (relu) v = fmaxf(v, 0.f);
            C[(long long)m * ldc + n] = v;
        }
    }
}

// ---------------- transposes ----------------
__global__ void transw_kernel(const float* __restrict__ in, float* __restrict__ out, int K, int N) {
    int idx = blockIdx.x * blockDim.x + threadIdx.x;
    if (idx >= K * N) return;
    int k = idx % K, n = idx / K;
    out[(long long)n * K + k] = in[(long long)k * N + n];
}

__global__ void trfeat_kernel(const float* __restrict__ in, float* __restrict__ out, int C, int HW) {
    int idx = blockIdx.x * blockDim.x + threadIdx.x;
    int total = BATCH * C * HW;
    if (idx >= total) return;
    int c = idx % C;
    int p = (idx / C) % HW;
    int b = idx / (C * HW);
    out[idx] = in[((long long)b * C + c) * HW + p];
}

// ---------------- GroupNorm ----------------
__global__ void gn_kernel(const float* __restrict__ in, float* __restrict__ out,
                          const float* __restrict__ sc, const float* __restrict__ bi,
                          int HW, int relu) {
    int b = blockIdx.y, g = blockIdx.x;
    long long base = ((long long)b * 256 + g * 8) * HW;
    int n = 8 * HW;
    float s = 0.f, s2 = 0.f;
    for (int i = threadIdx.x; i < n; i += blockDim.x) {
        float v = in[base + i];
        s += v;
        s2 += v * v;
    }
    __shared__ float sh0[256], sh1[256];
    sh0[threadIdx.x] = s;
    sh1[threadIdx.x] = s2;
    __syncthreads();
    for (int st = 128; st > 0; st >>= 1) {
        if (threadIdx.x < st) {
            sh0[threadIdx.x] += sh0[threadIdx.x + st];
            sh1[threadIdx.x] += sh1[threadIdx.x + st];
        }
        __syncthreads();
    }
    float mean = sh0[0] / n;
    float var = sh1[0] / n - mean * mean;
    float rstd = rsqrtf(var + 1e-5f);
    for (int i = threadIdx.x; i < n; i += blockDim.x) {
        int c = g * 8 + i / HW;
        float v = (in[base + i] - mean) * rstd * sc[c] + bi[c];
        if (relu) v = fmaxf(v, 0.f);
        out[base + i] = v;
    }
}

__global__ void addpool_kernel(const float* __restrict__ lat, const float* __restrict__ prev,
                               float* __restrict__ out, int H, int W) {
    int idx = blockIdx.x * blockDim.x + threadIdx.x;
    int total = BATCH * 256 * H * W;
    if (idx >= total) return;
    int x = idx % W;
    int y = (idx / W) % H;
    int bc = idx / (W * H);
    const float* p = prev + (long long)bc * 4 * H * W;
    int W2 = 2 * W;
    float v = 0.25f * (p[(2 * y) * W2 + 2 * x] + p[(2 * y) * W2 + 2 * x + 1] +
                       p[(2 * y + 1) * W2 + 2 * x] + p[(2 * y + 1) * W2 + 2 * x + 1]);
    out[idx] = lat[idx] + v;
}

// im2col old layout (level 3): col[b][ck][p]
__global__ void im2col_kernel(const float* __restrict__ in, float* __restrict__ col,
                              int H, int W) {
    int idx = blockIdx.x * blockDim.x + threadIdx.x;
    int HW = H * W;
    int total = BATCH * 2304 * HW;
    if (idx >= total) return;
    int p = idx % HW;
    int ck = (idx / HW) % 2304;
    int b = idx / (HW * 2304);
    int c = ck / 9, kk = ck % 9;
    int y = p / W + kk / 3 - 1;
    int x = p % W + kk % 3 - 1;
    float v = 0.f;
    if (y >= 0 && y < H && x >= 0 && x < W)
        v = in[((long long)b * 256 + c) * HW + y * W + x];
    col[idx] = v;
}

// im2col K-major: col[(b*HW+p)*2304 + ck]
__global__ void im2col_pc_kernel(const float* __restrict__ in, float* __restrict__ col,
                                 int H, int W) {
    int idx = blockIdx.x * blockDim.x + threadIdx.x;
    int HW = H * W;
    long long total = (long long)BATCH * HW * 2304;
    if (idx >= total) return;
    int ck = idx % 2304;
    int p = (idx / 2304) % HW;
    int b = idx / (2304 * HW);
    int c = ck / 9, kk = ck % 9;
    int y = p / W + kk / 3 - 1;
    int x = p % W + kk % 3 - 1;
    float v = 0.f;
    if (y >= 0 && y < H && x >= 0 && x < W)
        v = in[((long long)b * 256 + c) * HW + y * W + x];
    col[idx] = v;
}

__global__ void to_src_kernel(const float* __restrict__ ms, float* __restrict__ src,
                              int HW, int loff) {
    int idx = blockIdx.x * blockDim.x + threadIdx.x;
    int total = BATCH * HW * 256;
    if (idx >= total) return;
    int c = idx & 255;
    int p = (idx >> 8) % HW;
    int b = idx / (256 * HW);
    src[((long long)b * STOT + loff + p) * 256 + c] = ms[((long long)b * 256 + c) * HW + p];
}

__global__ void from_src_kernel(const float* __restrict__ src, float* __restrict__ out,
                                int HW, int loff) {
    int idx = blockIdx.x * blockDim.x + threadIdx.x;
    int total = BATCH * 256 * HW;
    if (idx >= total) return;
    int p = idx % HW;
    int c = (idx / HW) % 256;
    int b = idx / (HW * 256);
    out[idx] = src[((long long)b * STOT + loff + p) * 256 + c];
}

__global__ void pos_kernel(float* __restrict__ pos, float* __restrict__ refp) {
    int idx = blockIdx.x * blockDim.x + threadIdx.x;
    if (idx >= STOT * 256) return;
    int k = idx & 255;
    int s = idx >> 8;
    int H, W, p;
    if (s < 4096) { H = 64; W = 64; p = s; }
    else if (s < 5120) { H = 32; W = 32; p = s - 4096; }
    else if (s < 5376) { H = 16; W = 16; p = s - 5120; }
    else { H = 8; W = 8; p = s - 5376; }
    int y = p / W, x = p % W;
    float v;
    int feat;
    const float scale = 6.28318f;
    if (k < 128) { v = (y + 1.0f) / (H + 1e-6f) * scale; feat = k; }
    else { v = (x + 1.0f) / (W + 1e-6f) * scale; feat = k - 128; }
    float dim_t = powf(10000.0f, (2.0f * (feat / 2)) / 128.0f);
    float a = v / dim_t;
    pos[idx] = (feat & 1) ? cosf(a) : sinf(a);
    if (k == 0) {
        refp[s * 2 + 0] = (x + 0.5f) / W;
        refp[s * 2 + 1] = (y + 0.5f) / H;
    }
}

__global__ void addq_kernel(const float* __restrict__ src, const float* __restrict__ pos,
                            float* __restrict__ q) {
    int idx = blockIdx.x * blockDim.x + threadIdx.x;
    int total = BATCH * STOT * 256;
    if (idx >= total) return;
    q[idx] = src[idx] + pos[idx % (STOT * 256)];
}

__global__ void softmax16_kernel(float* __restrict__ aw) {
    int t = blockIdx.x * blockDim.x + threadIdx.x;
    int total = BATCH * STOT * NHEAD;
    if (t >= total) return;
    int bs = t / NHEAD, h = t % NHEAD;
    float* a = aw + (long long)bs * 128 + h * 16;
    float mx = -1e30f;
#pragma unroll
    for (int j = 0; j < 16; j++) mx = fmaxf(mx, a[j]);
    float e[16], sum = 0.f;
#pragma unroll
    for (int j = 0; j < 16; j++) { e[j] = __expf(a[j] - mx); sum += e[j]; }
    float inv = 1.0f / sum;
#pragma unroll
    for (int j = 0; j < 16; j++) a[j] = e[j] * inv;
}

__global__ void deform_kernel(const float* __restrict__ val, const float* __restrict__ off,
                              const float* __restrict__ aw, const float* __restrict__ refp,
                              float* __restrict__ out) {
    int gw = (blockIdx.x * blockDim.x + threadIdx.x) >> 5;
    int lane = threadIdx.x & 31;
    if (gw >= BATCH * STOT * NHEAD) return;
    int h = gw % NHEAD;
    int s = (gw / NHEAD) % STOT;
    int b = gw / (NHEAD * STOT);

    const int HWl[4] = {64, 32, 16, 8};
    const int loffs[4] = {0, 4096, 5120, 5376};
    float rx = refp[s * 2], ry = refp[s * 2 + 1];
    const float* offp = off + ((long long)(b * STOT + s)) * 256 + h * 32;
    const float* awp = aw + ((long long)(b * STOT + s)) * 128 + h * 16;
    float acc = 0.f;
#pragma unroll
    for (int l = 0; l < 4; l++) {
        int W = HWl[l], H = HWl[l], lo = loffs[l];
        float fW = (float)W, fH = (float)H;
#pragma unroll
        for (int p = 0; p < 4; p++) {
            float ox = offp[(l * 4 + p) * 2 + 0];
            float oy = offp[(l * 4 + p) * 2 + 1];
            float x = (rx + ox / fW) * fW - 0.5f;
            float y = (ry + oy / fH) * fH - 0.5f;
            float x0f = floorf(x), y0f = floorf(y);
            int x0 = (int)x0f, y0 = (int)y0f;
            float wx1 = x - x0f, wy1 = y - y0f;
            float wx0 = 1.f - wx1, wy0 = 1.f - wy1;
            float a = awp[l * 4 + p];
            float smp = 0.f;
#pragma unroll
            for (int cy = 0; cy < 2; cy++) {
#pragma unroll
                for (int cx = 0; cx < 2; cx++) {
                    int xi = x0 + cx, yi = y0 + cy;
                    if (xi >= 0 && xi < W && yi >= 0 && yi < H) {
                        float wgt = (cx ? wx1 : wx0) * (cy ? wy1 : wy0);
                        smp += wgt * val[((long long)(b * STOT + lo + yi * W + xi)) * 256 + h * 32 + lane];
                    }
                }
            }
            acc += a * smp;
        }
    }
    out[((long long)(b * STOT + s)) * 256 + h * 32 + lane] = acc;
}

__global__ void ln_res_kernel(float* __restrict__ src, const float* __restrict__ delta,
                              const float* __restrict__ sc, const float* __restrict__ bi) {
    long long base = (long long)blockIdx.x * 256;
    int t = threadIdx.x;
    float v = src[base + t] + delta[base + t];
    __shared__ float sh[256];
    sh[t] = v;
    __syncthreads();
    for (int s = 128; s > 0; s >>= 1) {
        if (t < s) sh[t] += sh[t + s];
        __syncthreads();
    }
    float mean = sh[0] * (1.0f / 256.0f);
    __syncthreads();
    float d = v - mean;
    sh[t] = d * d;
    __syncthreads();
    for (int s = 128; s > 0; s >>= 1) {
        if (t < s) sh[t] += sh[t + s];
        __syncthreads();
    }
    float var = sh[0] * (1.0f / 256.0f);
    src[base + t] = d * rsqrtf(var + 1e-5f) * sc[t] + bi[t];
}

// ---------------- host orchestration ----------------
extern "C" void kernel_launch(void* const* d_in, const int* in_sizes, int n_in,
                              void* d_out, int out_size) {
    const float* feat[4] = {(const float*)d_in[0], (const float*)d_in[1],
                            (const float*)d_in[2], (const float*)d_in[3]};
    const float* latw[4] = {(const float*)d_in[4], (const float*)d_in[5],
                            (const float*)d_in[6], (const float*)d_in[7]};
    const float* lat_gn_s = (const float*)d_in[8];
    const float* lat_gn_b = (const float*)d_in[9];
    const float* out_w = (const float*)d_in[10];
    const float* out_gn_s = (const float*)d_in[11];
    const float* out_gn_b = (const float*)d_in[12];
    const float* off_w = (const float*)d_in[13];
    const float* off_b = (const float*)d_in[14];
    const float* aw_w = (const float*)d_in[15];
    const float* aw_b = (const float*)d_in[16];
    const float* val_w = (const float*)d_in[17];
    const float* val_b = (const float*)d_in[18];
    const float* proj_w = (const float*)d_in[19];
    const float* proj_b = (const float*)d_in[20];
    const float* ffn1_w = (const float*)d_in[21];
    const float* ffn1_b = (const float*)d_in[22];
    const float* ffn2_w = (const float*)d_in[23];
    const float* ffn2_b = (const float*)d_in[24];
    const float* ln1_s = (const float*)d_in[25];
    const float* ln1_b = (const float*)d_in[26];
    const float* ln2_s = (const float*)d_in[27];
    const float* ln2_b = (const float*)d_in[28];
    const float* mask_w = (const float*)d_in[29];
    const float* mask_b = (const float*)d_in[30];

    float *lat, *o, *col, *ft, *wt, *ms, *src, *pos, *refp, *q, *val, *off, *aw, *attn, *tmp, *ffn;
    cudaGetSymbolAddress((void**)&lat, g_lat);
    cudaGetSymbolAddress((void**)&o, g_o);
    cudaGetSymbolAddress((void**)&col, g_col);
    cudaGetSymbolAddress((void**)&ft, g_ft);
    cudaGetSymbolAddress((void**)&wt, g_wt);
    cudaGetSymbolAddress((void**)&ms, g_ms);
    cudaGetSymbolAddress((void**)&src, g_src);
    cudaGetSymbolAddress((void**)&pos, g_pos);
    cudaGetSymbolAddress((void**)&refp, g_refpt);
    cudaGetSymbolAddress((void**)&q, g_q);
    cudaGetSymbolAddress((void**)&val, g_val);
    cudaGetSymbolAddress((void**)&off, g_off);
    cudaGetSymbolAddress((void**)&aw, g_aw);
    cudaGetSymbolAddress((void**)&attn, g_attn);
    cudaGetSymbolAddress((void**)&tmp, g_tmp);
    cudaGetSymbolAddress((void**)&ffn, g_ffn);

    // wt layout: val[0], off[65536], aw[131072 (128x256)], proj[163840],
    //            ffn1[229376 (2048x256)], ffn2[753664 (256x2048)]
    float* wt_val = wt;
    float* wt_off = wt + 65536;
    float* wt_aw = wt + 131072;
    float* wt_proj = wt + 163840;
    float* wt_f1 = wt + 229376;
    float* wt_f2 = wt + 753664;

    transw_kernel<<<(65536 + 255) / 256, 256>>>(val_w, wt_val, 256, 256);
    transw_kernel<<<(65536 + 255) / 256, 256>>>(off_w, wt_off, 256, 256);
    transw_kernel<<<(32768 + 255) / 256, 256>>>(aw_w, wt_aw, 256, 128);
    transw_kernel<<<(65536 + 255) / 256, 256>>>(proj_w, wt_proj, 256, 256);
    transw_kernel<<<(524288 + 255) / 256, 256>>>(ffn1_w, wt_f1, 256, 2048);
    transw_kernel<<<(524288 + 255) / 256, 256>>>(ffn2_w, wt_f2, 2048, 256);

    const int Hh[4] = {64, 32, 16, 8};
    const int HW[4] = {4096, 1024, 256, 64};
    const int Cin[4] = {256, 512, 1024, 2048};
    const int loff[4] = {0, 4096, 5120, 5376};
    long long msoff[4];
    msoff[0] = 0;
    for (int l = 1; l < 4; l++) msoff[l] = msoff[l - 1] + (long long)BATCH * 256 * HW[l - 1];

    // ---------- FPN ----------
    for (int l = 0; l < 4; l++) {
        if (l < 3) {
            int tot = BATCH * Cin[l] * HW[l];
            trfeat_kernel<<<(tot + 255) / 256, 256>>>(feat[l], ft, Cin[l], HW[l]);
            gx<<<dim3(HW[l] / 128, 2, BATCH), 256>>>(
                latw[l], ft, lat, Cin[l], Cin[l], Cin[l], HW[l],
                0LL, (long long)HW[l] * Cin[l], (long long)256 * HW[l], nullptr, 0, 0);
        } else {
            gemm64<<<dim3(1, 4, BATCH), 256>>>(latw[l], feat[l], lat, 256, HW[l], Cin[l],
                                               Cin[l], HW[l], HW[l],
                                               0LL, (long long)Cin[l] * HW[l],
                                               (long long)256 * HW[l], nullptr, 0, 0);
        }
        gn_kernel<<<dim3(32, BATCH), 256>>>(lat, lat, lat_gn_s + l * 256, lat_gn_b + l * 256,
                                            HW[l], 0);
        const float* oin = lat;
        if (l > 0) {
            int tot = BATCH * 256 * HW[l];
            addpool_kernel<<<(tot + 255) / 256, 256>>>(lat, ms + msoff[l - 1], o, Hh[l], Hh[l]);
            oin = o;
        }
        if (l < 3) {
            long long totc = (long long)BATCH * HW[l] * 2304;
            im2col_pc_kernel<<<(int)((totc + 255) / 256), 256>>>(oin, col, Hh[l], Hh[l]);
            gx<<<dim3(HW[l] / 128, 2, BATCH), 256>>>(
                out_w + (long long)l * 256 * 2304, col, lat, 2304, 2304, 2304, HW[l],
                0LL, (long long)HW[l] * 2304, (long long)256 * HW[l], nullptr, 0, 0);
        } else {
            int totc = BATCH * 2304 * HW[l];
            im2col_kernel<<<(totc + 255) / 256, 256>>>(oin, col, Hh[l], Hh[l]);
            gemm64<<<dim3(1, 4, BATCH), 256>>>(out_w + (long long)l * 256 * 2304, col, lat,
                                               256, HW[l], 2304, 2304, HW[l], HW[l],
                                               0LL, (long long)2304 * HW[l],
                                               (long long)256 * HW[l], nullptr, 0, 0);
        }
        gn_kernel<<<dim3(32, BATCH), 256>>>(lat, ms + msoff[l], out_gn_s + l * 256,
                                            out_gn_b + l * 256, HW[l], 1);
        int tots = BATCH * 256 * HW[l];
        to_src_kernel<<<(tots + 255) / 256, 256>>>(ms + msoff[l], src, HW[l], loff[l]);
    }

    // ---------- pos / ref ----------
    pos_kernel<<<(STOT * 256 + 255) / 256, 256>>>(pos, refp);

    // ---------- encoder layers ----------
    const int BS = BATCH * STOT;  // 10880 = 85 * 128
    for (int it = 0; it < NLAYER; it++) {
        int tot = BS * 256;
        addq_kernel<<<(tot + 255) / 256, 256>>>(src, pos, q);
        gx<<<dim3(2, 85), 256>>>(src, wt_val, val, 256, 256, 256, 256,
                                 0LL, 0LL, 0LL, val_b, 2, 0);
        gx<<<dim3(2, 85), 256>>>(q, wt_off, off, 256, 256, 256, 256,
                                 0LL, 0LL, 0LL, off_b, 2, 0);
        gx<<<dim3(1, 85), 256>>>(q, wt_aw, aw, 256, 256, 256, 128,
                                 0LL, 0LL, 0LL, aw_b, 2, 0);
        softmax16_kernel<<<(BS * NHEAD + 255) / 256, 256>>>(aw);
        deform_kernel<<<BS * NHEAD / 8, 256>>>(val, off, aw, refp, attn);
        gx<<<dim3(2, 85), 256>>>(attn, wt_proj, tmp, 256, 256, 256, 256,
                                 0LL, 0LL, 0LL, proj_b, 2, 0);
        ln_res_kernel<<<BS, 256>>>(src, tmp, ln1_s, ln1_b);
        gx<<<dim3(16, 85), 256>>>(src, wt_f1, ffn, 256, 256, 256, 2048,
                                  0LL, 0LL, 0LL, ffn1_b, 2, 1);
        gx<<<dim3(2, 85), 256>>>(ffn, wt_f2, tmp, 2048, 2048, 2048, 256,
                                 0LL, 0LL, 0LL, ffn2_b, 2, 0);
        ln_res_kernel<<<BS, 256>>>(src, tmp, ln2_s, ln2_b);
    }

    // ---------- outputs ----------
    float* outp = (float*)d_out;
    long long ooff[5];
    ooff[0] = 0;
    ooff[1] = ooff[0] + (long long)BATCH * 256 * 4096;
    ooff[2] = ooff[1] + (long long)BATCH * 256 * 4096;
    ooff[3] = ooff[2] + (long long)BATCH * 256 * 1024;
    ooff[4] = ooff[3] + (long long)BATCH * 256 * 256;
    for (int l = 0; l < 4; l++) {
        int tot = BATCH * 256 * HW[l];
        from_src_kernel<<<(tot + 255) / 256, 256>>>(src, outp + ooff[l + 1], HW[l], loff[l]);
    }
    // mask_feat: A = mask_w [256,256], B = src level-0 rows [4096,256] per batch
    gx<<<dim3(32, 2, BATCH), 256>>>(
        mask_w, src, outp, 256, 256, 256, 4096,
        0LL, (long long)STOT * 256, (long long)256 * 4096, mask_b, 1, 0);
}

// round 17
// speedup vs baseline: 1.1641x; 1.0184x over previous
#include <cuda_runtime.h>
#include <cuda_bf16.h>
#include <math.h>
#include <stdint.h>

#define BATCH 2
#define NHEAD 8
#define NLAYER 6
#define STOT 5440   // 4096+1024+256+64

// ---------------- scratch (static device globals; no runtime allocation) ----------------
__device__ float g_lat[BATCH * 256 * 4096];
__device__ float g_o[BATCH * 256 * 4096];
__device__ float g_col[BATCH * 2304 * 4096];
__device__ float g_ft[BATCH * 4096 * 256];
__device__ float g_wt[1310720];
__device__ float g_ms[BATCH * 256 * STOT];
__device__ float g_src[BATCH * STOT * 256];
__device__ float g_pos[STOT * 256];
__device__ float g_refpt[STOT * 2];
__device__ float g_q[BATCH * STOT * 256];
__device__ float g_val[BATCH * STOT * 256];
__device__ float g_off[BATCH * STOT * 256];
__device__ float g_aw[BATCH * STOT * 128];
__device__ float g_attn[BATCH * STOT * 256];
__device__ float g_tmp[BATCH * STOT * 256];
__device__ float g_ffn[BATCH * STOT * 2048];

// ---------------- helpers ----------------
__device__ __forceinline__ uint32_t smem_u32(const void* p) {
    uint32_t a;
    asm("{ .reg .u64 t; cvta.to.shared.u64 t, %1; cvt.u32.u64 %0, t; }" : "=r"(a) : "l"(p));
    return a;
}
__device__ __forceinline__ void ldm_x4(uint32_t& r0, uint32_t& r1, uint32_t& r2, uint32_t& r3,
                                       uint32_t addr) {
    asm volatile("ldmatrix.sync.aligned.m8n8.x4.shared.b16 {%0,%1,%2,%3}, [%4];"
                 : "=r"(r0), "=r"(r1), "=r"(r2), "=r"(r3) : "r"(addr));
}
__device__ __forceinline__ void mma_bf16(float* d, const uint32_t* a, const uint32_t* b) {
    asm volatile(
        "mma.sync.aligned.m16n8k16.row.col.f32.bf16.bf16.f32 "
        "{%0,%1,%2,%3}, {%4,%5,%6,%7}, {%8,%9}, {%0,%1,%2,%3};"
        : "+f"(d[0]), "+f"(d[1]), "+f"(d[2]), "+f"(d[3])
        : "r"(a[0]), "r"(a[1]), "r"(a[2]), "r"(a[3]), "r"(b[0]), "r"(b[1]));
}

// ============ HMMA bf16x3 GEMM (record-holder core — DO NOT TOUCH) ============
// C[M,N] = A[M,K] * B[N,K]^T (+bias)(+relu). A,B fp32 in GMEM, K-major rows.
// grid = (N/128, M/128, batch), 256 threads. K % 32 == 0.
#define PITCH 40   // bf16 elems per smem row (32 data + 8 pad -> 80B pitch, ldmatrix conflict-free)

__global__ __launch_bounds__(256)
void gx(const float* __restrict__ A, const float* __restrict__ B, float* __restrict__ C,
        int K, int lda, int ldb, int ldc,
        long long sA, long long sB, long long sC,
        const float* __restrict__ bias, int bias_mode, int relu) {
    A += (long long)blockIdx.z * sA;
    B += (long long)blockIdx.z * sB;
    C += (long long)blockIdx.z * sC;

    __shared__ __align__(16) uint16_t AsH[128][PITCH];
    __shared__ __align__(16) uint16_t AsL[128][PITCH];
    __shared__ __align__(16) uint16_t BsH[128][PITCH];
    __shared__ __align__(16) uint16_t BsL[128][PITCH];

    int tid = threadIdx.x;
    int lane = tid & 31, w = tid >> 5;
    int row0 = blockIdx.y * 128, col0 = blockIdx.x * 128;

    int lr = tid >> 3;          // 0..31
    int lk = (tid & 7) * 4;     // 0,4,...,28
    const float* Ap = A + (long long)(row0 + lr) * lda + lk;
    const float* Bp = B + (long long)(col0 + lr) * ldb + lk;

    int m0 = (w >> 1) * 32;
    int n0 = (w & 1) * 64;

    uint32_t ah_base = smem_u32(&AsH[0][0]);
    uint32_t al_base = smem_u32(&AsL[0][0]);
    uint32_t bh_base = smem_u32(&BsH[0][0]);
    uint32_t bl_base = smem_u32(&BsL[0][0]);

    int lrow = ((lane >> 3) & 1) * 8 + (lane & 7);
    int lcol = ((lane >> 4) & 1) * 8;

    float acc[2][8][4];
#pragma unroll
    for (int i = 0; i < 2; i++)
#pragma unroll
        for (int j = 0; j < 8; j++)
#pragma unroll
            for (int q = 0; q < 4; q++) acc[i][j][q] = 0.f;

    int nst = K >> 5;
    float4 pa[4], pb[4];
#pragma unroll
    for (int i = 0; i < 4; i++) {
        pa[i] = *(const float4*)(Ap + (long long)i * 32 * lda);
        pb[i] = *(const float4*)(Bp + (long long)i * 32 * ldb);
    }

    for (int s = 0; s < nst; s++) {
#pragma unroll
        for (int i = 0; i < 4; i++) {
            int r = lr + i * 32;
            float4 v = pa[i];
            __nv_bfloat162 h01 = __floats2bfloat162_rn(v.x, v.y);
            __nv_bfloat162 h23 = __floats2bfloat162_rn(v.z, v.w);
            __nv_bfloat162 l01 = __floats2bfloat162_rn(v.x - __bfloat162float(h01.x),
                                                       v.y - __bfloat162float(h01.y));
            __nv_bfloat162 l23 = __floats2bfloat162_rn(v.z - __bfloat162float(h23.x),
                                                       v.w - __bfloat162float(h23.y));
            *(uint32_t*)&AsH[r][lk] = *(uint32_t*)&h01;
            *(uint32_t*)&AsH[r][lk + 2] = *(uint32_t*)&h23;
            *(uint32_t*)&AsL[r][lk] = *(uint32_t*)&l01;
            *(uint32_t*)&AsL[r][lk + 2] = *(uint32_t*)&l23;

            v = pb[i];
            h01 = __floats2bfloat162_rn(v.x, v.y);
            h23 = __floats2bfloat162_rn(v.z, v.w);
            l01 = __floats2bfloat162_rn(v.x - __bfloat162float(h01.x),
                                        v.y - __bfloat162float(h01.y));
            l23 = __floats2bfloat162_rn(v.z - __bfloat162float(h23.x),
                                        v.w - __bfloat162float(h23.y));
            *(uint32_t*)&BsH[r][lk] = *(uint32_t*)&h01;
            *(uint32_t*)&BsH[r][lk + 2] = *(uint32_t*)&h23;
            *(uint32_t*)&BsL[r][lk] = *(uint32_t*)&l01;
            *(uint32_t*)&BsL[r][lk + 2] = *(uint32_t*)&l23;
        }
        __syncthreads();

        if (s + 1 < nst) {
            int k0 = (s + 1) << 5;
#pragma unroll
            for (int i = 0; i < 4; i++) {
                pa[i] = *(const float4*)(Ap + (long long)i * 32 * lda + k0);
                pb[i] = *(const float4*)(Bp + (long long)i * 32 * ldb + k0);
            }
        }

#pragma unroll
        for (int kk = 0; kk < 2; kk++) {
            int kc = kk * 16 + lcol;
            uint32_t aH[2][4], aL[2][4], bH[8][2], bL[8][2];
#pragma unroll
            for (int ma = 0; ma < 2; ma++) {
                uint32_t off = (uint32_t)((m0 + ma * 16 + lrow) * PITCH + kc) * 2;
                ldm_x4(aH[ma][0], aH[ma][1], aH[ma][2], aH[ma][3], ah_base + off);
                ldm_x4(aL[ma][0], aL[ma][1], aL[ma][2], aL[ma][3], al_base + off);
            }
#pragma unroll
            for (int ng = 0; ng < 4; ng++) {
                uint32_t off = (uint32_t)((n0 + ng * 16 + lrow) * PITCH + kc) * 2;
                uint32_t r0, r1, r2, r3;
                ldm_x4(r0, r1, r2, r3, bh_base + off);
                bH[ng * 2][0] = r0; bH[ng * 2][1] = r2;
                bH[ng * 2 + 1][0] = r1; bH[ng * 2 + 1][1] = r3;
                ldm_x4(r0, r1, r2, r3, bl_base + off);
                bL[ng * 2][0] = r0; bL[ng * 2][1] = r2;
                bL[ng * 2 + 1][0] = r1; bL[ng * 2 + 1][1] = r3;
            }
#pragma unroll
            for (int ma = 0; ma < 2; ma++)
#pragma unroll
                for (int na = 0; na < 8; na++) {
                    mma_bf16(acc[ma][na], aH[ma], bH[na]);
                    mma_bf16(acc[ma][na], aH[ma], bL[na]);
                    mma_bf16(acc[ma][na], aL[ma], bH[na]);
                }
        }
        __syncthreads();
    }

    int g = lane >> 2;
    int t2 = (lane & 3) * 2;
#pragma unroll
    for (int ma = 0; ma < 2; ma++) {
#pragma unroll
        for (int na = 0; na < 8; na++) {
            int mA = row0 + m0 + ma * 16 + g;
            int nA = col0 + n0 + na * 8 + t2;
            float b0 = 0.f, b1 = 0.f;
            if (bias_mode == 2) { b0 = bias[nA]; b1 = bias[nA + 1]; }
            float bmA = (bias_mode == 1) ? bias[mA] : 0.f;
            float bmB = (bias_mode == 1) ? bias[mA + 8] : 0.f;
            float2 o0, o1;
            o0.x = acc[ma][na][0] + bmA + b0;
            o0.y = acc[ma][na][1] + bmA + b1;
            o1.x = acc[ma][na][2] + bmB + b0;
            o1.y = acc[ma][na][3] + bmB + b1;
            if (relu) {
                o0.x = fmaxf(o0.x, 0.f); o0.y = fmaxf(o0.y, 0.f);
                o1.x = fmaxf(o1.x, 0.f); o1.y = fmaxf(o1.y, 0.f);
            }
            *(float2*)(C + (long long)mA * ldc + nA) = o0;
            *(float2*)(C + (long long)(mA + 8) * ldc + nA) = o1;
        }
    }
}

// ---------------- small fp32 GEMM (64x64x16), level 3 ----------------
__global__ void gemm64(const float* __restrict__ A, const float* __restrict__ B,
                       float* __restrict__ C,
                       int M, int N, int K, int lda, int ldb, int ldc,
                       long long sA, long long sB, long long sC,
                       const float* __restrict__ bias, int bias_mode, int relu) {
    A += (long long)blockIdx.z * sA;
    B += (long long)blockIdx.z * sB;
    C += (long long)blockIdx.z * sC;

    __shared__ float As[16][64];
    __shared__ float Bs[16][64];

    int tid = threadIdx.x;
    int tr = tid >> 4, tc = tid & 15;
    int row0 = blockIdx.y * 64, col0 = blockIdx.x * 64;

    int ar = tid >> 2;
    int ak = (tid & 3) * 4;
    int bk = tid >> 4;
    int bn = (tid & 15) * 4;

    float acc[4][4] = {};

    for (int k0 = 0; k0 < K; k0 += 16) {
        float4 a4 = *(const float4*)(A + (long long)(row0 + ar) * lda + k0 + ak);
        As[ak + 0][ar] = a4.x;
        As[ak + 1][ar] = a4.y;
        As[ak + 2][ar] = a4.z;
        As[ak + 3][ar] = a4.w;
        float4 b4 = *(const float4*)(B + (long long)(k0 + bk) * ldb + col0 + bn);
        *(float4*)&Bs[bk][bn] = b4;
        __syncthreads();

#pragma unroll
        for (int k = 0; k < 16; k++) {
            float4 av = *(const float4*)&As[k][tr * 4];
            float4 bv = *(const float4*)&Bs[k][tc * 4];
            float aa[4] = {av.x, av.y, av.z, av.w};
            float bb[4] = {bv.x, bv.y, bv.z, bv.w};
#pragma unroll
            for (int i = 0; i < 4; i++)
#pragma unroll
                for (int j = 0; j < 4; j++) acc[i][j] += aa[i] * bb[j];
        }
        __syncthreads();
    }

#pragma unroll
    for (int i = 0; i < 4; i++) {
        int m = row0 + tr * 4 + i;
        float bm = (bias_mode == 1) ? bias[m] : 0.f;
#pragma unroll
        for (int j = 0; j < 4; j++) {
            int n = col0 + tc * 4 + j;
            float v = acc[i][j] + bm + ((bias_mode == 2) ? bias[n] : 0.f);
            if (relu) v = fmaxf(v, 0.f);
            C[(long long)m * ldc + n] = v;
        }
    }
}

// ---------------- transposes ----------------
__global__ void transw_kernel(const float* __restrict__ in, float* __restrict__ out, int K, int N) {
    int idx = blockIdx.x * blockDim.x + threadIdx.x;
    if (idx >= K * N) return;
    int k = idx % K, n = idx / K;
    out[(long long)n * K + k] = in[(long long)k * N + n];
}

__global__ void trfeat_kernel(const float* __restrict__ in, float* __restrict__ out, int C, int HW) {
    int idx = blockIdx.x * blockDim.x + threadIdx.x;
    int total = BATCH * C * HW;
    if (idx >= total) return;
    int c = idx % C;
    int p = (idx / C) % HW;
    int b = idx / (C * HW);
    out[idx] = in[((long long)b * C + c) * HW + p];
}

// ---------------- GroupNorm ----------------
__global__ void gn_kernel(const float* __restrict__ in, float* __restrict__ out,
                          const float* __restrict__ sc, const float* __restrict__ bi,
                          int HW, int relu) {
    int b = blockIdx.y, g = blockIdx.x;
    long long base = ((long long)b * 256 + g * 8) * HW;
    int n = 8 * HW;
    float s = 0.f, s2 = 0.f;
    for (int i = threadIdx.x; i < n; i += blockDim.x) {
        float v = in[base + i];
        s += v;
        s2 += v * v;
    }
    __shared__ float sh0[256], sh1[256];
    sh0[threadIdx.x] = s;
    sh1[threadIdx.x] = s2;
    __syncthreads();
    for (int st = 128; st > 0; st >>= 1) {
        if (threadIdx.x < st) {
            sh0[threadIdx.x] += sh0[threadIdx.x + st];
            sh1[threadIdx.x] += sh1[threadIdx.x + st];
        }
        __syncthreads();
    }
    float mean = sh0[0] / n;
    float var = sh1[0] / n - mean * mean;
    float rstd = rsqrtf(var + 1e-5f);
    for (int i = threadIdx.x; i < n; i += blockDim.x) {
        int c = g * 8 + i / HW;
        float v = (in[base + i] - mean) * rstd * sc[c] + bi[c];
        if (relu) v = fmaxf(v, 0.f);
        out[base + i] = v;
    }
}

__global__ void addpool_kernel(const float* __restrict__ lat, const float* __restrict__ prev,
                               float* __restrict__ out, int H, int W) {
    int idx = blockIdx.x * blockDim.x + threadIdx.x;
    int total = BATCH * 256 * H * W;
    if (idx >= total) return;
    int x = idx % W;
    int y = (idx / W) % H;
    int bc = idx / (W * H);
    const float* p = prev + (long long)bc * 4 * H * W;
    int W2 = 2 * W;
    float v = 0.25f * (p[(2 * y) * W2 + 2 * x] + p[(2 * y) * W2 + 2 * x + 1] +
                       p[(2 * y + 1) * W2 + 2 * x] + p[(2 * y + 1) * W2 + 2 * x + 1]);
    out[idx] = lat[idx] + v;
}

// im2col old layout (level 3): col[b][ck][p]
__global__ void im2col_kernel(const float* __restrict__ in, float* __restrict__ col,
                              int H, int W) {
    int idx = blockIdx.x * blockDim.x + threadIdx.x;
    int HW = H * W;
    int total = BATCH * 2304 * HW;
    if (idx >= total) return;
    int p = idx % HW;
    int ck = (idx / HW) % 2304;
    int b = idx / (HW * 2304);
    int c = ck / 9, kk = ck % 9;
    int y = p / W + kk / 3 - 1;
    int x = p % W + kk % 3 - 1;
    float v = 0.f;
    if (y >= 0 && y < H && x >= 0 && x < W)
        v = in[((long long)b * 256 + c) * HW + y * W + x];
    col[idx] = v;
}

// im2col K-major: col[(b*HW+p)*2304 + ck]
__global__ void im2col_pc_kernel(const float* __restrict__ in, float* __restrict__ col,
                                 int H, int W) {
    int idx = blockIdx.x * blockDim.x + threadIdx.x;
    int HW = H * W;
    long long total = (long long)BATCH * HW * 2304;
    if (idx >= total) return;
    int ck = idx % 2304;
    int p = (idx / 2304) % HW;
    int b = idx / (2304 * HW);
    int c = ck / 9, kk = ck % 9;
    int y = p / W + kk / 3 - 1;
    int x = p % W + kk % 3 - 1;
    float v = 0.f;
    if (y >= 0 && y < H && x >= 0 && x < W)
        v = in[((long long)b * 256 + c) * HW + y * W + x];
    col[idx] = v;
}

__global__ void to_src_kernel(const float* __restrict__ ms, float* __restrict__ src,
                              int HW, int loff) {
    int idx = blockIdx.x * blockDim.x + threadIdx.x;
    int total = BATCH * HW * 256;
    if (idx >= total) return;
    int c = idx & 255;
    int p = (idx >> 8) % HW;
    int b = idx / (256 * HW);
    src[((long long)b * STOT + loff + p) * 256 + c] = ms[((long long)b * 256 + c) * HW + p];
}

__global__ void from_src_kernel(const float* __restrict__ src, float* __restrict__ out,
                                int HW, int loff) {
    int idx = blockIdx.x * blockDim.x + threadIdx.x;
    int total = BATCH * 256 * HW;
    if (idx >= total) return;
    int p = idx % HW;
    int c = (idx / HW) % 256;
    int b = idx / (HW * 256);
    out[idx] = src[((long long)b * STOT + loff + p) * 256 + c];
}

__global__ void pos_kernel(float* __restrict__ pos, float* __restrict__ refp) {
    int idx = blockIdx.x * blockDim.x + threadIdx.x;
    if (idx >= STOT * 256) return;
    int k = idx & 255;
    int s = idx >> 8;
    int H, W, p;
    if (s < 4096) { H = 64; W = 64; p = s; }
    else if (s < 5120) { H = 32; W = 32; p = s - 4096; }
    else if (s < 5376) { H = 16; W = 16; p = s - 5120; }
    else { H = 8; W = 8; p = s - 5376; }
    int y = p / W, x = p % W;
    float v;
    int feat;
    const float scale = 6.28318f;
    if (k < 128) { v = (y + 1.0f) / (H + 1e-6f) * scale; feat = k; }
    else { v = (x + 1.0f) / (W + 1e-6f) * scale; feat = k - 128; }
    float dim_t = powf(10000.0f, (2.0f * (feat / 2)) / 128.0f);
    float a = v / dim_t;
    pos[idx] = (feat & 1) ? cosf(a) : sinf(a);
    if (k == 0) {
        refp[s * 2 + 0] = (x + 0.5f) / W;
        refp[s * 2 + 1] = (y + 0.5f) / H;
    }
}

__global__ void addq_kernel(const float* __restrict__ src, const float* __restrict__ pos,
                            float* __restrict__ q) {
    int idx = blockIdx.x * blockDim.x + threadIdx.x;
    int total = BATCH * STOT * 256;
    if (idx >= total) return;
    q[idx] = src[idx] + pos[idx % (STOT * 256)];
}

// ms-deformable sampling with fused in-register softmax: one warp per (b,s,head)
__global__ void deform_kernel(const float* __restrict__ val, const float* __restrict__ off,
                              const float* __restrict__ aw, const float* __restrict__ refp,
                              float* __restrict__ out) {
    int gw = (blockIdx.x * blockDim.x + threadIdx.x) >> 5;
    int lane = threadIdx.x & 31;
    if (gw >= BATCH * STOT * NHEAD) return;
    int h = gw % NHEAD;
    int s = (gw / NHEAD) % STOT;
    int b = gw / (NHEAD * STOT);

    const int HWl[4] = {64, 32, 16, 8};
    const int loffs[4] = {0, 4096, 5120, 5376};
    float rx = refp[s * 2], ry = refp[s * 2 + 1];
    const float* offp = off + ((long long)(b * STOT + s)) * 256 + h * 32;
    const float* awp = aw + ((long long)(b * STOT + s)) * 128 + h * 16;

    // in-register softmax over the 16 logits (warp-broadcast loads)
    float awv[16];
    float mx = -1e30f;
#pragma unroll
    for (int j = 0; j < 16; j++) { awv[j] = awp[j]; mx = fmaxf(mx, awv[j]); }
    float sum = 0.f;
#pragma unroll
    for (int j = 0; j < 16; j++) { awv[j] = __expf(awv[j] - mx); sum += awv[j]; }
    float inv = 1.0f / sum;

    float acc = 0.f;
#pragma unroll
    for (int l = 0; l < 4; l++) {
        int W = HWl[l], H = HWl[l], lo = loffs[l];
        float fW = (float)W, fH = (float)H;
#pragma unroll
        for (int p = 0; p < 4; p++) {
            float ox = offp[(l * 4 + p) * 2 + 0];
            float oy = offp[(l * 4 + p) * 2 + 1];
            float x = (rx + ox / fW) * fW - 0.5f;
            float y = (ry + oy / fH) * fH - 0.5f;
            float x0f = floorf(x), y0f = floorf(y);
            int x0 = (int)x0f, y0 = (int)y0f;
            float wx1 = x - x0f, wy1 = y - y0f;
            float wx0 = 1.f - wx1, wy0 = 1.f - wy1;
            float a = awv[l * 4 + p] * inv;
            float smp = 0.f;
#pragma unroll
            for (int cy = 0; cy < 2; cy++) {
#pragma unroll
                for (int cx = 0; cx < 2; cx++) {
                    int xi = x0 + cx, yi = y0 + cy;
                    if (xi >= 0 && xi < W && yi >= 0 && yi < H) {
                        float wgt = (cx ? wx1 : wx0) * (cy ? wy1 : wy0);
                        smp += wgt * val[((long long)(b * STOT + lo + yi * W + xi)) * 256 + h * 32 + lane];
                    }
                }
            }
            acc += a * smp;
        }
    }
    out[((long long)(b * STOT + s)) * 256 + h * 32 + lane] = acc;
}

// src = LayerNorm(src + delta); warp-per-row, 8 rows per block
__global__ void ln_res_kernel(float* __restrict__ src, const float* __restrict__ delta,
                              const float* __restrict__ sc, const float* __restrict__ bi) {
    int row = blockIdx.x * 8 + (threadIdx.x >> 5);
    int lane = threadIdx.x & 31;
    long long base = (long long)row * 256 + lane * 8;

    float v[8];
    *(float4*)&v[0] = *(const float4*)(src + base);
    *(float4*)&v[4] = *(const float4*)(src + base + 4);
    float4 d0 = *(const float4*)(delta + base);
    float4 d1 = *(const float4*)(delta + base + 4);
    v[0] += d0.x; v[1] += d0.y; v[2] += d0.z; v[3] += d0.w;
    v[4] += d1.x; v[5] += d1.y; v[6] += d1.z; v[7] += d1.w;

    float s = 0.f;
#pragma unroll
    for (int j = 0; j < 8; j++) s += v[j];
#pragma unroll
    for (int st = 16; st > 0; st >>= 1) s += __shfl_xor_sync(0xffffffff, s, st);
    float mean = s * (1.0f / 256.0f);

    float s2 = 0.f;
#pragma unroll
    for (int j = 0; j < 8; j++) { float d = v[j] - mean; s2 += d * d; }
#pragma unroll
    for (int st = 16; st > 0; st >>= 1) s2 += __shfl_xor_sync(0xffffffff, s2, st);
    float rstd = rsqrtf(s2 * (1.0f / 256.0f) + 1e-5f);

    int c = lane * 8;
    float4 o0, o1;
    o0.x = (v[0] - mean) * rstd * sc[c + 0] + bi[c + 0];
    o0.y = (v[1] - mean) * rstd * sc[c + 1] + bi[c + 1];
    o0.z = (v[2] - mean) * rstd * sc[c + 2] + bi[c + 2];
    o0.w = (v[3] - mean) * rstd * sc[c + 3] + bi[c + 3];
    o1.x = (v[4] - mean) * rstd * sc[c + 4] + bi[c + 4];
    o1.y = (v[5] - mean) * rstd * sc[c + 5] + bi[c + 5];
    o1.z = (v[6] - mean) * rstd * sc[c + 6] + bi[c + 6];
    o1.w = (v[7] - mean) * rstd * sc[c + 7] + bi[c + 7];
    *(float4*)(src + base) = o0;
    *(float4*)(src + base + 4) = o1;
}

// ---------------- host orchestration ----------------
extern "C" void kernel_launch(void* const* d_in, const int* in_sizes, int n_in,
                              void* d_out, int out_size) {
    const float* feat[4] = {(const float*)d_in[0], (const float*)d_in[1],
                            (const float*)d_in[2], (const float*)d_in[3]};
    const float* latw[4] = {(const float*)d_in[4], (const float*)d_in[5],
                            (const float*)d_in[6], (const float*)d_in[7]};
    const float* lat_gn_s = (const float*)d_in[8];
    const float* lat_gn_b = (const float*)d_in[9];
    const float* out_w = (const float*)d_in[10];
    const float* out_gn_s = (const float*)d_in[11];
    const float* out_gn_b = (const float*)d_in[12];
    const float* off_w = (const float*)d_in[13];
    const float* off_b = (const float*)d_in[14];
    const float* aw_w = (const float*)d_in[15];
    const float* aw_b = (const float*)d_in[16];
    const float* val_w = (const float*)d_in[17];
    const float* val_b = (const float*)d_in[18];
    const float* proj_w = (const float*)d_in[19];
    const float* proj_b = (const float*)d_in[20];
    const float* ffn1_w = (const float*)d_in[21];
    const float* ffn1_b = (const float*)d_in[22];
    const float* ffn2_w = (const float*)d_in[23];
    const float* ffn2_b = (const float*)d_in[24];
    const float* ln1_s = (const float*)d_in[25];
    const float* ln1_b = (const float*)d_in[26];
    const float* ln2_s = (const float*)d_in[27];
    const float* ln2_b = (const float*)d_in[28];
    const float* mask_w = (const float*)d_in[29];
    const float* mask_b = (const float*)d_in[30];

    float *lat, *o, *col, *ft, *wt, *ms, *src, *pos, *refp, *q, *val, *off, *aw, *attn, *tmp, *ffn;
    cudaGetSymbolAddress((void**)&lat, g_lat);
    cudaGetSymbolAddress((void**)&o, g_o);
    cudaGetSymbolAddress((void**)&col, g_col);
    cudaGetSymbolAddress((void**)&ft, g_ft);
    cudaGetSymbolAddress((void**)&wt, g_wt);
    cudaGetSymbolAddress((void**)&ms, g_ms);
    cudaGetSymbolAddress((void**)&src, g_src);
    cudaGetSymbolAddress((void**)&pos, g_pos);
    cudaGetSymbolAddress((void**)&refp, g_refpt);
    cudaGetSymbolAddress((void**)&q, g_q);
    cudaGetSymbolAddress((void**)&val, g_val);
    cudaGetSymbolAddress((void**)&off, g_off);
    cudaGetSymbolAddress((void**)&aw, g_aw);
    cudaGetSymbolAddress((void**)&attn, g_attn);
    cudaGetSymbolAddress((void**)&tmp, g_tmp);
    cudaGetSymbolAddress((void**)&ffn, g_ffn);

    // wt layout: val[0], off[65536], aw[131072 (128x256)], proj[163840],
    //            ffn1[229376 (2048x256)], ffn2[753664 (256x2048)]
    float* wt_val = wt;
    float* wt_off = wt + 65536;
    float* wt_aw = wt + 131072;
    float* wt_proj = wt + 163840;
    float* wt_f1 = wt + 229376;
    float* wt_f2 = wt + 753664;

    transw_kernel<<<(65536 + 255) / 256, 256>>>(val_w, wt_val, 256, 256);
    transw_kernel<<<(65536 + 255) / 256, 256>>>(off_w, wt_off, 256, 256);
    transw_kernel<<<(32768 + 255) / 256, 256>>>(aw_w, wt_aw, 256, 128);
    transw_kernel<<<(65536 + 255) / 256, 256>>>(proj_w, wt_proj, 256, 256);
    transw_kernel<<<(524288 + 255) / 256, 256>>>(ffn1_w, wt_f1, 256, 2048);
    transw_kernel<<<(524288 + 255) / 256, 256>>>(ffn2_w, wt_f2, 2048, 256);

    const int Hh[4] = {64, 32, 16, 8};
    const int HW[4] = {4096, 1024, 256, 64};
    const int Cin[4] = {256, 512, 1024, 2048};
    const int loff[4] = {0, 4096, 5120, 5376};
    long long msoff[4];
    msoff[0] = 0;
    for (int l = 1; l < 4; l++) msoff[l] = msoff[l - 1] + (long long)BATCH * 256 * HW[l - 1];

    // ---------- FPN ----------
    for (int l = 0; l < 4; l++) {
        if (l < 3) {
            int tot = BATCH * Cin[l] * HW[l];
            trfeat_kernel<<<(tot + 255) / 256, 256>>>(feat[l], ft, Cin[l], HW[l]);
            gx<<<dim3(HW[l] / 128, 2, BATCH), 256>>>(
                latw[l], ft, lat, Cin[l], Cin[l], Cin[l], HW[l],
                0LL, (long long)HW[l] * Cin[l], (long long)256 * HW[l], nullptr, 0, 0);
        } else {
            gemm64<<<dim3(1, 4, BATCH), 256>>>(latw[l], feat[l], lat, 256, HW[l], Cin[l],
                                               Cin[l], HW[l], HW[l],
                                               0LL, (long long)Cin[l] * HW[l],
                                               (long long)256 * HW[l], nullptr, 0, 0);
        }
        gn_kernel<<<dim3(32, BATCH), 256>>>(lat, lat, lat_gn_s + l * 256, lat_gn_b + l * 256,
                                            HW[l], 0);
        const float* oin = lat;
        if (l > 0) {
            int tot = BATCH * 256 * HW[l];
            addpool_kernel<<<(tot + 255) / 256, 256>>>(lat, ms + msoff[l - 1], o, Hh[l], Hh[l]);
            oin = o;
        }
        if (l < 3) {
            long long totc = (long long)BATCH * HW[l] * 2304;
            im2col_pc_kernel<<<(int)((totc + 255) / 256), 256>>>(oin, col, Hh[l], Hh[l]);
            gx<<<dim3(HW[l] / 128, 2, BATCH), 256>>>(
                out_w + (long long)l * 256 * 2304, col, lat, 2304, 2304, 2304, HW[l],
                0LL, (long long)HW[l] * 2304, (long long)256 * HW[l], nullptr, 0, 0);
        } else {
            int totc = BATCH * 2304 * HW[l];
            im2col_kernel<<<(totc + 255) / 256, 256>>>(oin, col, Hh[l], Hh[l]);
            gemm64<<<dim3(1, 4, BATCH), 256>>>(out_w + (long long)l * 256 * 2304, col, lat,
                                               256, HW[l], 2304, 2304, HW[l], HW[l],
                                               0LL, (long long)2304 * HW[l],
                                               (long long)256 * HW[l], nullptr, 0, 0);
        }
        gn_kernel<<<dim3(32, BATCH), 256>>>(lat, ms + msoff[l], out_gn_s + l * 256,
                                            out_gn_b + l * 256, HW[l], 1);
        int tots = BATCH * 256 * HW[l];
        to_src_kernel<<<(tots + 255) / 256, 256>>>(ms + msoff[l], src, HW[l], loff[l]);
    }

    // ---------- pos / ref ----------
    pos_kernel<<<(STOT * 256 + 255) / 256, 256>>>(pos, refp);

    // ---------- encoder layers ----------
    const int BS = BATCH * STOT;  // 10880 = 85 * 128
    for (int it = 0; it < NLAYER; it++) {
        int tot = BS * 256;
        addq_kernel<<<(tot + 255) / 256, 256>>>(src, pos, q);
        gx<<<dim3(2, 85), 256>>>(src, wt_val, val, 256, 256, 256, 256,
                                 0LL, 0LL, 0LL, val_b, 2, 0);
        gx<<<dim3(2, 85), 256>>>(q, wt_off, off, 256, 256, 256, 256,
                                 0LL, 0LL, 0LL, off_b, 2, 0);
        gx<<<dim3(1, 85), 256>>>(q, wt_aw, aw, 256, 256, 256, 128,
                                 0LL, 0LL, 0LL, aw_b, 2, 0);
        deform_kernel<<<BS * NHEAD / 8, 256>>>(val, off, aw, refp, attn);
        gx<<<dim3(2, 85), 256>>>(attn, wt_proj, tmp, 256, 256, 256, 256,
                                 0LL, 0LL, 0LL, proj_b, 2, 0);
        ln_res_kernel<<<BS / 8, 256>>>(src, tmp, ln1_s, ln1_b);
        gx<<<dim3(16, 85), 256>>>(src, wt_f1, ffn, 256, 256, 256, 2048,
                                  0LL, 0LL, 0LL, ffn1_b, 2, 1);
        gx<<<dim3(2, 85), 256>>>(ffn, wt_f2, tmp, 2048, 2048, 2048, 256,
                                 0LL, 0LL, 0LL, ffn2_b, 2, 0);
        ln_res_kernel<<<BS / 8, 256>>>(src, tmp, ln2_s, ln2_b);
    }

    // ---------- outputs ----------
    float* outp = (float*)d_out;
    long long ooff[5];
    ooff[0] = 0;
    ooff[1] = ooff[0] + (long long)BATCH * 256 * 4096;
    ooff[2] = ooff[1] + (long long)BATCH * 256 * 4096;
    ooff[3] = ooff[2] + (long long)BATCH * 256 * 1024;
    ooff[4] = ooff[3] + (long long)BATCH * 256 * 256;
    for (int l = 0; l < 4; l++) {
        int tot = BATCH * 256 * HW[l];
        from_src_kernel<<<(tot + 255) / 256, 256>>>(src, outp + ooff[l + 1], HW[l], loff[l]);
    }
    // mask_feat: A = mask_w [256,256], B = src level-0 rows [4096,256] per batch
    gx<<<dim3(32, 2, BATCH), 256>>>(
        mask_w, src, outp, 256, 256, 256, 4096,
        0LL, (long long)STOT * 256, (long long)256 * 4096, mask_b, 1, 0);
}